// round 14
// baseline (speedup 1.0000x reference)
#include <cuda_runtime.h>

#define WN 128
#define NMAXN 100000
#define EMAX 600000
#define GMAX 64

// ---------------- scratch ----------------
__device__ float g_B0[(size_t)NMAXN * WN];
__device__ float g_B1[(size_t)NMAXN * WN];
__device__ float g_B2[(size_t)NMAXN * WN];
__device__ unsigned g_S1h[(size_t)NMAXN * 64];
__device__ unsigned g_S1l[(size_t)NMAXN * 64];
__device__ unsigned g_Wsh[4 * 8192];
__device__ unsigned g_Wsl[4 * 8192];
__device__ float g_dinv[NMAXN];
__device__ int   g_cnt[NMAXN];
__device__ int   g_rowtmp[NMAXN];
__device__ int   g_rowptr[NMAXN + 1];
__device__ int   g_cursor[NMAXN];
__device__ int   g_bsum[128];
__device__ int   g_boff[128];
__device__ int   g_scan_done;
__device__ int   g_csrc[EMAX];
__device__ float g_cdinv[EMAX];
__device__ float g_stats[2 * WN];
__device__ float g_pooled[GMAX * WN];

// ---------------- bf16 2-split helpers ----------------
__device__ __forceinline__ void split_bf16(float x, unsigned short& h, float& r) {
    asm("cvt.rn.bf16.f32 %0, %1;" : "=h"(h) : "f"(x));
    r = x - __uint_as_float(((unsigned)h) << 16);
}
__device__ __forceinline__ unsigned packf_bf16x2(float lo_, float hi_) {
    unsigned u;
    asm("cvt.rn.bf16x2.f32 %0, %1, %2;" : "=r"(u) : "f"(hi_), "f"(lo_));
    return u;
}
__device__ __forceinline__ void split_pair(float a, float b, unsigned& hi, unsigned& lo) {
    unsigned short ha, hb;
    float ra, rb;
    split_bf16(a, ha, ra);
    split_bf16(b, hb, rb);
    hi = ((unsigned)hb << 16) | (unsigned)ha;
    lo = packf_bf16x2(ra, rb);
}
__device__ __forceinline__ void mma_bf16(float* c, const unsigned* a, const unsigned* b) {
    asm volatile(
        "mma.sync.aligned.m16n8k16.row.col.f32.bf16.bf16.f32 "
        "{%0,%1,%2,%3}, {%4,%5,%6,%7}, {%8,%9}, {%0,%1,%2,%3};"
        : "+f"(c[0]), "+f"(c[1]), "+f"(c[2]), "+f"(c[3])
        : "r"(a[0]), "r"(a[1]), "r"(a[2]), "r"(a[3]), "r"(b[0]), "r"(b[1]));
}
__device__ __forceinline__ void cp16(unsigned* dst, const void* src, bool pred) {
    unsigned d = (unsigned)__cvta_generic_to_shared(dst);
    int sz = pred ? 16 : 0;
    asm volatile("cp.async.cg.shared.global [%0], [%1], 16, %2;"
                 :: "r"(d), "l"(src), "r"(sz));
}
__device__ __forceinline__ void cp_commit() {
    asm volatile("cp.async.commit_group;");
}
template<int NG>
__device__ __forceinline__ void cp_wait() {
    asm volatile("cp.async.wait_group %0;" :: "n"(NG));
}
// k-pair permutation within each 8-group: (0,4,1,5,2,6,3,7) so fragment
// partners (p, p+4) are adjacent -> single LDS.64 per fragment pair.
__device__ __forceinline__ int kperm(int kp) {
    int g = kp & ~7;
    int p = kp & 7;
    return g + ((p < 4) ? (p * 2) : ((p - 4) * 2 + 1));
}

// ---------------- degree / dinv ----------------
__global__ void deg_kernel(const int* __restrict__ dst, int E) {
    int e = blockIdx.x * blockDim.x + threadIdx.x;
    if (e < E) atomicAdd(&g_cnt[dst[e]], 1);
}

__global__ void dinv_kernel(int N) {
    int i = blockIdx.x * blockDim.x + threadIdx.x;
    if (i < N) g_dinv[i] = rsqrtf((float)g_cnt[i] + 1.0f);
}

// ---------------- CSR build: scan1 with fused last-block finalize ----------------
__global__ void scan1_kernel(int N) {
    __shared__ int sm[1024];
    __shared__ int isLast;
    int tid = threadIdx.x;
    int i = blockIdx.x * 1024 + tid;
    int v = (i < N) ? g_cnt[i] : 0;
    sm[tid] = v;
    __syncthreads();
#pragma unroll
    for (int o = 1; o < 1024; o <<= 1) {
        int t = 0;
        if (tid >= o) t = sm[tid - o];
        __syncthreads();
        if (tid >= o) sm[tid] += t;
        __syncthreads();
    }
    if (i < N) g_rowtmp[i] = sm[tid];
    if (tid == 1023) g_bsum[blockIdx.x] = sm[1023];
    __threadfence();
    if (tid == 0) isLast = (atomicAdd(&g_scan_done, 1) == (int)gridDim.x - 1);
    __syncthreads();
    if (isLast) {
        __shared__ int sm2[128];
        int nb = gridDim.x;
        int v2 = 0;
        if (tid < 128) {
            v2 = (tid < nb) ? g_bsum[tid] : 0;
            sm2[tid] = v2;
        }
        __syncthreads();
#pragma unroll
        for (int o = 1; o < 128; o <<= 1) {
            int u = 0;
            if (tid < 128 && tid >= o) u = sm2[tid - o];
            __syncthreads();
            if (tid < 128 && tid >= o) sm2[tid] += u;
            __syncthreads();
        }
        if (tid < 128 && tid < nb) g_boff[tid] = sm2[tid] - v2;
        if (tid == 127) g_rowptr[N] = sm2[127];
        if (tid == 0) g_scan_done = 0;
    }
}

__global__ void scan3_kernel(int N) {
    int i = blockIdx.x * blockDim.x + threadIdx.x;
    if (i < N) {
        int rp = g_rowtmp[i] - g_cnt[i] + g_boff[i >> 10];
        g_rowptr[i] = rp;
        g_cursor[i] = rp;
    }
}

__global__ void bin_kernel(const int* __restrict__ src, const int* __restrict__ dst, int E) {
    int e = blockIdx.x * blockDim.x + threadIdx.x;
    if (e >= E) return;
    int s = src[e], d = dst[e];
    int pos = atomicAdd(&g_cursor[d], 1);
    g_csrc[pos] = s;
    g_cdinv[pos] = g_dinv[s];
}

// ---------------- W split (k-pair permuted layout) ----------------
__global__ void wsplit_kernel(const float* __restrict__ W, unsigned* __restrict__ oh,
                              unsigned* __restrict__ ol, int K) {
    int i = blockIdx.x * blockDim.x + threadIdx.x;
    int KP = K >> 1;
    if (i >= 128 * KP) return;
    int c = i / KP, kp = i % KP;
    unsigned h, l;
    split_pair(W[(size_t)(2 * kp) * WN + c], W[(size_t)(2 * kp + 1) * WN + c], h, l);
    int pos = (size_t)c * KP + kperm(kp);
    oh[pos] = h;
    ol[pos] = l;
}

// ---------------- gather_x (32-wide) ----------------
__global__ void gatherx_kernel(const float* __restrict__ x, float* __restrict__ out, int N) {
    int t = blockIdx.x * blockDim.x + threadIdx.x;
    int w = t >> 5;
    if (w >= N) return;
    int lane = t & 31;
    int p0 = g_rowptr[w], p1 = g_rowptr[w + 1];
    float acc = 0.f;
    int e = p0;
    for (; e + 4 <= p1; e += 4) {
        int s0 = g_csrc[e], s1 = g_csrc[e + 1], s2 = g_csrc[e + 2], s3 = g_csrc[e + 3];
        float n0 = g_cdinv[e], n1 = g_cdinv[e + 1], n2 = g_cdinv[e + 2], n3 = g_cdinv[e + 3];
        acc = fmaf(x[(size_t)s0 * 32 + lane], n0, acc);
        acc = fmaf(x[(size_t)s1 * 32 + lane], n1, acc);
        acc = fmaf(x[(size_t)s2 * 32 + lane], n2, acc);
        acc = fmaf(x[(size_t)s3 * 32 + lane], n3, acc);
    }
    for (; e < p1; ++e)
        acc = fmaf(x[(size_t)g_csrc[e] * 32 + lane], g_cdinv[e], acc);
    float dv = g_dinv[w];
    out[(size_t)w * 32 + lane] = fmaf(acc, dv, x[(size_t)w * 32 + lane] * dv * dv);
}

// ---------------- gather -> split (permuted kpair positions) ----------------
__global__ void gather_split_kernel(const float* __restrict__ h, const float* __restrict__ bias,
                                    unsigned* __restrict__ oh, unsigned* __restrict__ ol, int N) {
    int t = blockIdx.x * blockDim.x + threadIdx.x;
    int w = t >> 5;
    if (w >= N) return;
    int lane = t & 31;
    int p0 = g_rowptr[w], p1 = g_rowptr[w + 1];
    float4 acc = make_float4(0.f, 0.f, 0.f, 0.f);
    int e = p0;
    for (; e + 4 <= p1; e += 4) {
        int s0 = g_csrc[e], s1 = g_csrc[e + 1], s2 = g_csrc[e + 2], s3 = g_csrc[e + 3];
        float n0 = g_cdinv[e], n1 = g_cdinv[e + 1], n2 = g_cdinv[e + 2], n3 = g_cdinv[e + 3];
        float4 v0 = ((const float4*)(h + (size_t)s0 * WN))[lane];
        float4 v1 = ((const float4*)(h + (size_t)s1 * WN))[lane];
        float4 v2 = ((const float4*)(h + (size_t)s2 * WN))[lane];
        float4 v3 = ((const float4*)(h + (size_t)s3 * WN))[lane];
        acc.x = fmaf(v0.x, n0, acc.x); acc.y = fmaf(v0.y, n0, acc.y);
        acc.z = fmaf(v0.z, n0, acc.z); acc.w = fmaf(v0.w, n0, acc.w);
        acc.x = fmaf(v1.x, n1, acc.x); acc.y = fmaf(v1.y, n1, acc.y);
        acc.z = fmaf(v1.z, n1, acc.z); acc.w = fmaf(v1.w, n1, acc.w);
        acc.x = fmaf(v2.x, n2, acc.x); acc.y = fmaf(v2.y, n2, acc.y);
        acc.z = fmaf(v2.z, n2, acc.z); acc.w = fmaf(v2.w, n2, acc.w);
        acc.x = fmaf(v3.x, n3, acc.x); acc.y = fmaf(v3.y, n3, acc.y);
        acc.z = fmaf(v3.z, n3, acc.z); acc.w = fmaf(v3.w, n3, acc.w);
    }
    for (; e < p1; ++e) {
        int s = g_csrc[e];
        float n = g_cdinv[e];
        float4 v = ((const float4*)(h + (size_t)s * WN))[lane];
        acc.x = fmaf(v.x, n, acc.x); acc.y = fmaf(v.y, n, acc.y);
        acc.z = fmaf(v.z, n, acc.z); acc.w = fmaf(v.w, n, acc.w);
    }
    float dv = g_dinv[w];
    float d2 = dv * dv;
    float4 hd = ((const float4*)(h + (size_t)w * WN))[lane];
    float4 b = ((const float4*)bias)[lane];
    float4 o;
    o.x = fmaxf(0.f, fmaf(acc.x, dv, fmaf(hd.x, d2, b.x)));
    o.y = fmaxf(0.f, fmaf(acc.y, dv, fmaf(hd.y, d2, b.y)));
    o.z = fmaxf(0.f, fmaf(acc.z, dv, fmaf(hd.z, d2, b.z)));
    o.w = fmaxf(0.f, fmaf(acc.w, dv, fmaf(hd.w, d2, b.w)));
    unsigned h0, l0, h1, l1;
    split_pair(o.x, o.y, h0, l0);
    split_pair(o.z, o.w, h1, l1);
    int q0 = kperm(lane * 2), q1 = kperm(lane * 2 + 1);
    oh[(size_t)w * 64 + q0] = h0;
    oh[(size_t)w * 64 + q1] = h1;
    ol[(size_t)w * 64 + q0] = l0;
    ol[(size_t)w * 64 + q1] = l1;
}

// ---------------- fused GEMM1+GEMM2: B0 = relu(Xs@W1 + b1) @ W2 ----------------
__global__ __launch_bounds__(256, 2) void gemm12_kernel(
        const float* __restrict__ Xs,
        const unsigned* __restrict__ W1h, const unsigned* __restrict__ W1l,
        const unsigned* __restrict__ W2h, const unsigned* __restrict__ W2l,
        const float* __restrict__ b1, float* __restrict__ C, int M) {
    constexpr int ST = 20;     // staging stride (conflict-free for LDS.64: residues all distinct)
    constexpr int ST2 = 68;    // T1 stride (>=64 kpairs; 68 mod 32 == 4 -> conflict-free)
    extern __shared__ unsigned smem[];
    unsigned* T1h = smem;                  // 128*68 = 8704
    unsigned* T1l = smem + 8704;
    unsigned* S   = smem + 17408;          // 10240 staging region

    int tid = threadIdx.x;
    int lane = tid & 31, wid = tid >> 5;
    int wm = wid >> 1, wn = wid & 1;
    int gr = lane >> 2;
    int row0 = blockIdx.x * 128;

    float acc[2][8][4];
#pragma unroll
    for (int mt = 0; mt < 2; ++mt)
#pragma unroll
        for (int nt = 0; nt < 8; ++nt)
#pragma unroll
            for (int q = 0; q < 4; ++q) acc[mt][nt][q] = 0.f;

    // compute one 32-k chunk; A/W in permuted layout -> uint2 fragment loads
    auto comp = [&](const unsigned* Ah, const unsigned* Al, int STa,
                    const unsigned* Wh, const unsigned* Wl) {
#pragma unroll
        for (int ks = 0; ks < 2; ++ks) {
            int ko = ks * 8 + 2 * (lane & 3);
            unsigned ah[2][4], al[2][4];
#pragma unroll
            for (int mt = 0; mt < 2; ++mt) {
                int r = wm * 32 + mt * 16 + gr;
                uint2 u0 = *(const uint2*)&Ah[r * STa + ko];
                uint2 u1 = *(const uint2*)&Ah[(r + 8) * STa + ko];
                ah[mt][0] = u0.x; ah[mt][1] = u1.x; ah[mt][2] = u0.y; ah[mt][3] = u1.y;
                uint2 v0 = *(const uint2*)&Al[r * STa + ko];
                uint2 v1 = *(const uint2*)&Al[(r + 8) * STa + ko];
                al[mt][0] = v0.x; al[mt][1] = v1.x; al[mt][2] = v0.y; al[mt][3] = v1.y;
            }
#pragma unroll
            for (int nh = 0; nh < 2; ++nh) {
                unsigned bh[4][2], bl[4][2];
#pragma unroll
                for (int j = 0; j < 4; ++j) {
                    int c = wn * 64 + (nh * 4 + j) * 8 + gr;
                    uint2 wb = *(const uint2*)&Wh[c * ST + ko];
                    bh[j][0] = wb.x; bh[j][1] = wb.y;
                    uint2 wc = *(const uint2*)&Wl[c * ST + ko];
                    bl[j][0] = wc.x; bl[j][1] = wc.y;
                }
#pragma unroll
                for (int mt = 0; mt < 2; ++mt)
#pragma unroll
                    for (int j = 0; j < 4; ++j) {
                        float* cc = acc[mt][nh * 4 + j];
                        mma_bf16(cc, al[mt], bh[j]);
                        mma_bf16(cc, ah[mt], bl[j]);
                        mma_bf16(cc, ah[mt], bh[j]);
                    }
            }
        }
    };

    // ---- phase 1: T1 = relu(Xs@W1 + b1) ----
    {
        unsigned* Axh = S;
        unsigned* Axl = S + 2560;
        unsigned* W1s = S + 5120;
        unsigned* W1t = S + 7680;
        for (int i = tid; i < 512; i += 256) {
            int c = i >> 2, q = (i & 3) * 4;
            cp16(&W1s[c * ST + q], &W1h[(size_t)c * 16 + q], true);
            cp16(&W1t[c * ST + q], &W1l[(size_t)c * 16 + q], true);
        }
        cp_commit();
        for (int i = tid; i < 1024; i += 256) {
            int r = i >> 3, q = i & 7;
            float4 v = make_float4(0.f, 0.f, 0.f, 0.f);
            if (row0 + r < M)
                v = *(const float4*)(Xs + (size_t)(row0 + r) * 32 + 4 * q);
            unsigned h0, l0, h1, l1;
            split_pair(v.x, v.y, h0, l0);
            split_pair(v.z, v.w, h1, l1);
            int q0 = kperm(2 * q), q1 = kperm(2 * q + 1);
            Axh[r * ST + q0] = h0; Axh[r * ST + q1] = h1;
            Axl[r * ST + q0] = l0; Axl[r * ST + q1] = l1;
        }
        cp_wait<0>();
        __syncthreads();
        comp(Axh, Axl, ST, W1s, W1t);
        __syncthreads();
    }

    auto issueW2 = [&](int ci, int s) {
        unsigned* Wh = S + s * 5120;
        unsigned* Wl = Wh + 2560;
        int kp0 = ci * 16;
        for (int i = tid; i < 512; i += 256) {
            int c = i >> 2, q = (i & 3) * 4;
            cp16(&Wh[c * ST + q], &W2h[(size_t)c * 64 + kp0 + q], true);
            cp16(&Wl[c * ST + q], &W2l[(size_t)c * 64 + kp0 + q], true);
        }
        cp_commit();
    };
    issueW2(0, 0);
    issueW2(1, 1);

    // epilogue-1: relu(acc + b1) -> split T1 (permuted positions); reset acc
    {
        float bv[16];
#pragma unroll
        for (int nt = 0; nt < 8; ++nt) {
            int col = wn * 64 + nt * 8 + (lane & 3) * 2;
            bv[nt * 2] = b1[col];
            bv[nt * 2 + 1] = b1[col + 1];
        }
#pragma unroll
        for (int mt = 0; mt < 2; ++mt)
#pragma unroll
            for (int h = 0; h < 2; ++h) {
                int r = wm * 32 + mt * 16 + gr + h * 8;
#pragma unroll
                for (int nt = 0; nt < 8; ++nt) {
                    int col = wn * 64 + nt * 8 + (lane & 3) * 2;
                    float v0 = fmaxf(0.f, acc[mt][nt][h * 2 + 0] + bv[nt * 2]);
                    float v1 = fmaxf(0.f, acc[mt][nt][h * 2 + 1] + bv[nt * 2 + 1]);
                    unsigned hh, ll;
                    split_pair(v0, v1, hh, ll);
                    int pos = kperm(col >> 1);
                    T1h[r * ST2 + pos] = hh;
                    T1l[r * ST2 + pos] = ll;
                }
            }
#pragma unroll
        for (int mt = 0; mt < 2; ++mt)
#pragma unroll
            for (int nt = 0; nt < 8; ++nt)
#pragma unroll
                for (int q = 0; q < 4; ++q) acc[mt][nt][q] = 0.f;
    }
    __syncthreads();

    // ---- phase 2: B0 = T1 @ W2, 4 chunks, double-buffered W2 ----
    // chunk ci consumes T1 kpairs [ci*16, ci*16+16) against W2 chunk ci
#pragma unroll
    for (int ci = 0; ci < 4; ++ci) {
        if (ci < 3) cp_wait<1>(); else cp_wait<0>();
        __syncthreads();
        comp(T1h + ci * 16, T1l + ci * 16, ST2,
             S + (ci & 1) * 5120, S + (ci & 1) * 5120 + 2560);
        __syncthreads();
        if (ci + 2 < 4) issueW2(ci + 2, ci & 1);
    }

    // epilogue-2: write f32 (no bias)
#pragma unroll
    for (int mt = 0; mt < 2; ++mt)
#pragma unroll
        for (int h = 0; h < 2; ++h) {
            int row = row0 + wm * 32 + mt * 16 + gr + h * 8;
            if (row >= M) continue;
#pragma unroll
            for (int nt = 0; nt < 8; ++nt) {
                int col = wn * 64 + nt * 8 + (lane & 3) * 2;
                *(float2*)(C + (size_t)row * WN + col) =
                    make_float2(acc[mt][nt][h * 2 + 0], acc[mt][nt][h * 2 + 1]);
            }
        }
}

// ---------------- 3x bf16-split tensor-core GEMM (GEMM3 / GEMM4) ----------------
template<int K, int PRO, bool INSPLIT, bool STATS, bool POOL>
__global__ __launch_bounds__(256, 2) void mma_gemm(
        const float* __restrict__ A,
        const unsigned* __restrict__ Agh, const unsigned* __restrict__ Agl,
        const unsigned* __restrict__ Wgh, const unsigned* __restrict__ Wgl,
        const float* __restrict__ bias, float* __restrict__ C,
        const float* __restrict__ bng, const float* __restrict__ bnb,
        const int* __restrict__ batch, int M) {
    constexpr int CH = 32;
    constexpr int KP = K / 2;
    constexpr int ST = 20;
    constexpr int NC = K / CH;
    constexpr int STAGE = 10240;
    extern __shared__ unsigned smem[];
    __shared__ float sstat[2 * WN];
    __shared__ float sbnp[2 * WN];

    int tid = threadIdx.x;
    int lane = tid & 31, wid = tid >> 5;
    int wm = wid >> 1, wn = wid & 1;
    int gr = lane >> 2;
    int row0 = blockIdx.x * 128;

    if (STATS) sstat[tid] = 0.f;
    if (PRO == 2) {
        if (tid < WN) {
            float inv = 1.0f / (float)M;
            float mu = g_stats[tid] * inv;
            float var = g_stats[WN + tid] * inv - mu * mu;
            float sc = bng[tid] * rsqrtf(var + 1e-5f);
            sbnp[tid] = sc;
            sbnp[WN + tid] = bnb[tid] - mu * sc;
        }
        __syncthreads();
    }

    float acc[2][8][4];
#pragma unroll
    for (int mt = 0; mt < 2; ++mt)
#pragma unroll
        for (int nt = 0; nt < 8; ++nt)
#pragma unroll
            for (int q = 0; q < 4; ++q) acc[mt][nt][q] = 0.f;

    auto issue = [&](int ci, int s) {
        unsigned* Ah = smem + s * STAGE;
        unsigned* Al = Ah + 2560;
        unsigned* Wh = Ah + 5120;
        unsigned* Wl = Ah + 7680;
        int kp0 = ci * (CH / 2);
#pragma unroll
        for (int i = tid; i < 512; i += 256) {
            int c = i >> 2, q = (i & 3) * 4;
            cp16(&Wh[c * ST + q], &Wgh[(size_t)c * KP + kp0 + q], true);
            cp16(&Wl[c * ST + q], &Wgl[(size_t)c * KP + kp0 + q], true);
        }
#pragma unroll
        for (int i = tid; i < 512; i += 256) {
            int r = i >> 2, q = (i & 3) * 4;
            bool ok = row0 + r < M;
            cp16(&Ah[r * ST + q], &Agh[(size_t)(row0 + r) * 64 + kp0 + q], ok);
            cp16(&Al[r * ST + q], &Agl[(size_t)(row0 + r) * 64 + kp0 + q], ok);
        }
        cp_commit();
    };

    auto compute = [&](int s) {
        unsigned* Ah = smem + s * STAGE;
        unsigned* Al = Ah + 2560;
        unsigned* Wh = Ah + 5120;
        unsigned* Wl = Ah + 7680;
#pragma unroll
        for (int ks = 0; ks < 2; ++ks) {
            int ko = ks * 8 + 2 * (lane & 3);
            unsigned ah[2][4], al[2][4];
#pragma unroll
            for (int mt = 0; mt < 2; ++mt) {
                int r = wm * 32 + mt * 16 + gr;
                uint2 u0 = *(const uint2*)&Ah[r * ST + ko];
                uint2 u1 = *(const uint2*)&Ah[(r + 8) * ST + ko];
                ah[mt][0] = u0.x; ah[mt][1] = u1.x; ah[mt][2] = u0.y; ah[mt][3] = u1.y;
                uint2 v0 = *(const uint2*)&Al[r * ST + ko];
                uint2 v1 = *(const uint2*)&Al[(r + 8) * ST + ko];
                al[mt][0] = v0.x; al[mt][1] = v1.x; al[mt][2] = v0.y; al[mt][3] = v1.y;
            }
#pragma unroll
            for (int nh = 0; nh < 2; ++nh) {
                unsigned bh[4][2], bl[4][2];
#pragma unroll
                for (int j = 0; j < 4; ++j) {
                    int c = wn * 64 + (nh * 4 + j) * 8 + gr;
                    uint2 wb = *(const uint2*)&Wh[c * ST + ko];
                    bh[j][0] = wb.x; bh[j][1] = wb.y;
                    uint2 wc = *(const uint2*)&Wl[c * ST + ko];
                    bl[j][0] = wc.x; bl[j][1] = wc.y;
                }
#pragma unroll
                for (int mt = 0; mt < 2; ++mt)
#pragma unroll
                    for (int j = 0; j < 4; ++j) {
                        float* cc = acc[mt][nh * 4 + j];
                        mma_bf16(cc, al[mt], bh[j]);
                        mma_bf16(cc, ah[mt], bl[j]);
                        mma_bf16(cc, ah[mt], bh[j]);
                    }
            }
        }
    };

    if (INSPLIT) {
        issue(0, 0);
#pragma unroll
        for (int ci = 0; ci < NC; ++ci) {
            if (ci + 1 < NC) {
                issue(ci + 1, (ci + 1) & 1);
                cp_wait<1>();
            } else {
                cp_wait<0>();
            }
            __syncthreads();
            compute(ci & 1);
            __syncthreads();
        }
    } else {
        unsigned* Ah = smem;
        unsigned* Al = smem + 2560;
        unsigned* Wh = smem + 5120;
        unsigned* Wl = smem + 7680;
        for (int kb = 0; kb < K; kb += CH) {
            int kp0 = kb >> 1;
            __syncthreads();
            for (int i = tid; i < 512; i += 256) {
                int c = i >> 2, q = (i & 3) * 4;
                *(uint4*)&Wh[c * ST + q] = *(const uint4*)&Wgh[(size_t)c * KP + kp0 + q];
                *(uint4*)&Wl[c * ST + q] = *(const uint4*)&Wgl[(size_t)c * KP + kp0 + q];
            }
            for (int i = tid; i < 128 * 8; i += 256) {
                int r = i >> 3, q = i & 7;
                float4 v = make_float4(0.f, 0.f, 0.f, 0.f);
                if (row0 + r < M)
                    v = *(const float4*)(A + (size_t)(row0 + r) * K + kb + 4 * q);
                if (PRO == 2) {
                    int kg = kb + 4 * q;
                    v.x = fmaxf(0.f, fmaf(v.x, sbnp[kg + 0], sbnp[WN + kg + 0]));
                    v.y = fmaxf(0.f, fmaf(v.y, sbnp[kg + 1], sbnp[WN + kg + 1]));
                    v.z = fmaxf(0.f, fmaf(v.z, sbnp[kg + 2], sbnp[WN + kg + 2]));
                    v.w = fmaxf(0.f, fmaf(v.w, sbnp[kg + 3], sbnp[WN + kg + 3]));
                }
                unsigned h0, l0, h1, l1;
                split_pair(v.x, v.y, h0, l0);
                split_pair(v.z, v.w, h1, l1);
                int q0 = kperm(2 * q), q1 = kperm(2 * q + 1);
                Ah[r * ST + q0] = h0; Ah[r * ST + q1] = h1;
                Al[r * ST + q0] = l0; Al[r * ST + q1] = l1;
            }
            __syncthreads();
            compute(0);
        }
    }

    // ---------------- epilogue ----------------
    if (POOL) {
        int rbase = row0 + wm * 32 + gr;
        int bt[4];
#pragma unroll
        for (int t = 0; t < 4; ++t) {
            int r = rbase + t * 8;
            bt[t] = (r < M) ? batch[r] : -1;
        }
        bool same = (bt[0] == bt[1]) && (bt[1] == bt[2]) && (bt[2] == bt[3]) && (bt[0] >= 0);
#pragma unroll
        for (int nt = 0; nt < 8; ++nt) {
#pragma unroll
            for (int c = 0; c < 2; ++c) {
                int col = wn * 64 + nt * 8 + (lane & 3) * 2 + c;
                float bb = bias[col];
                float v[4];
                v[0] = fmaxf(0.f, acc[0][nt][c] + bb);
                v[1] = fmaxf(0.f, acc[0][nt][2 + c] + bb);
                v[2] = fmaxf(0.f, acc[1][nt][c] + bb);
                v[3] = fmaxf(0.f, acc[1][nt][2 + c] + bb);
                if (same) {
                    float m = fmaxf(fmaxf(v[0], v[1]), fmaxf(v[2], v[3]));
                    atomicMax((int*)&g_pooled[(size_t)bt[0] * WN + col], __float_as_int(m));
                } else {
#pragma unroll
                    for (int t = 0; t < 4; ++t)
                        if (bt[t] >= 0)
                            atomicMax((int*)&g_pooled[(size_t)bt[t] * WN + col],
                                      __float_as_int(v[t]));
                }
            }
        }
        return;
    }

    float ss[16], sq[16];
    if (STATS) {
#pragma unroll
        for (int i = 0; i < 16; ++i) { ss[i] = 0.f; sq[i] = 0.f; }
    }

#pragma unroll
    for (int mt = 0; mt < 2; ++mt) {
#pragma unroll
        for (int h = 0; h < 2; ++h) {
            int row = row0 + wm * 32 + mt * 16 + gr + h * 8;
            bool ok = row < M;
#pragma unroll
            for (int nt = 0; nt < 8; ++nt) {
                int col = wn * 64 + nt * 8 + (lane & 3) * 2;
                float b0 = bias ? bias[col] : 0.f;
                float b1 = bias ? bias[col + 1] : 0.f;
                float o0 = acc[mt][nt][h * 2 + 0] + b0;
                float o1 = acc[mt][nt][h * 2 + 1] + b1;
                if (ok)
                    *(float2*)(C + (size_t)row * WN + col) = make_float2(o0, o1);
                if (STATS) {
                    if (!ok) { o0 = 0.f; o1 = 0.f; }
                    ss[nt * 2 + 0] += o0; sq[nt * 2 + 0] += o0 * o0;
                    ss[nt * 2 + 1] += o1; sq[nt * 2 + 1] += o1 * o1;
                }
            }
        }
    }

    if (STATS) {
#pragma unroll
        for (int i = 0; i < 16; ++i) {
#pragma unroll
            for (int o = 4; o <= 16; o <<= 1) {
                ss[i] += __shfl_xor_sync(0xffffffffu, ss[i], o);
                sq[i] += __shfl_xor_sync(0xffffffffu, sq[i], o);
            }
        }
        if (lane < 4) {
#pragma unroll
            for (int nt = 0; nt < 8; ++nt)
#pragma unroll
                for (int c = 0; c < 2; ++c) {
                    int col = wn * 64 + nt * 8 + lane * 2 + c;
                    atomicAdd(&sstat[col], ss[nt * 2 + c]);
                    atomicAdd(&sstat[WN + col], sq[nt * 2 + c]);
                }
        }
        __syncthreads();
        atomicAdd(&g_stats[tid], sstat[tid]);
    }
}

// ---------------- final tiny MLP ----------------
__global__ void final_kernel(const float* __restrict__ W5, const float* __restrict__ b5,
                             const float* __restrict__ g2, const float* __restrict__ be2,
                             const float* __restrict__ W6, const float* __restrict__ b6,
                             float* __restrict__ out, int G) {
    __shared__ float W5s[WN * 64];
    __shared__ float ys[GMAX][65];
    __shared__ float sc[64], sh[64];
    int tid = threadIdx.x;
    for (int i = tid; i < WN * 64; i += 256) W5s[i] = W5[i];
    __syncthreads();

    int g = tid & 63;
    int jb = tid >> 6;
    float acc[16];
#pragma unroll
    for (int j = 0; j < 16; ++j) acc[j] = 0.f;
    if (g < G) {
        for (int k = 0; k < WN; ++k) {
            float p = g_pooled[(size_t)g * WN + k];
#pragma unroll
            for (int j = 0; j < 16; ++j)
                acc[j] = fmaf(p, W5s[k * 64 + jb * 16 + j], acc[j]);
        }
#pragma unroll
        for (int j = 0; j < 16; ++j)
            ys[g][jb * 16 + j] = acc[j] + b5[jb * 16 + j];
    }
    __syncthreads();

    if (tid < 64) {
        float s = 0.f, q = 0.f;
        for (int r = 0; r < G; ++r) {
            float v = ys[r][tid];
            s += v;
            q += v * v;
        }
        float inv = 1.0f / (float)G;
        float mu = s * inv;
        float var = q * inv - mu * mu;
        float scale = g2[tid] * rsqrtf(var + 1e-5f);
        sc[tid] = scale;
        sh[tid] = be2[tid] - mu * scale;
    }
    __syncthreads();

    if (tid < G) {
        float o = b6[0];
        for (int j = 0; j < 64; ++j) {
            float v = fmaxf(0.f, fmaf(ys[tid][j], sc[j], sh[j]));
            o = fmaf(v, W6[j], o);
        }
        out[tid] = o;
    }
}

// ---------------- launch ----------------
extern "C" void kernel_launch(void* const* d_in, const int* in_sizes, int n_in,
                              void* d_out, int out_size) {
    const float* x   = (const float*)d_in[0];
    const int*   ei  = (const int*)d_in[1];
    const int*   bat = (const int*)d_in[2];
    const float* W1  = (const float*)d_in[3];
    const float* b1  = (const float*)d_in[4];
    const float* W2  = (const float*)d_in[5];
    const float* b2  = (const float*)d_in[6];
    const float* W3  = (const float*)d_in[7];
    const float* b3  = (const float*)d_in[8];
    const float* g1  = (const float*)d_in[9];
    const float* be1 = (const float*)d_in[10];
    const float* W4  = (const float*)d_in[11];
    const float* b4  = (const float*)d_in[12];
    const float* W5  = (const float*)d_in[13];
    const float* b5  = (const float*)d_in[14];
    const float* g2  = (const float*)d_in[15];
    const float* be2 = (const float*)d_in[16];
    const float* W6  = (const float*)d_in[17];
    const float* b6  = (const float*)d_in[18];

    int N = in_sizes[2];
    int E = in_sizes[1] / 2;
    int G = out_size;
    const int* src = ei;
    const int* dst = ei + E;

    float *B0, *B1, *B2;
    unsigned *S1h, *S1l, *Wsh, *Wsl;
    void *pcnt, *pstats, *ppooled;
    cudaGetSymbolAddress((void**)&B0, g_B0);
    cudaGetSymbolAddress((void**)&B1, g_B1);
    cudaGetSymbolAddress((void**)&B2, g_B2);
    cudaGetSymbolAddress((void**)&S1h, g_S1h);
    cudaGetSymbolAddress((void**)&S1l, g_S1l);
    cudaGetSymbolAddress((void**)&Wsh, g_Wsh);
    cudaGetSymbolAddress((void**)&Wsl, g_Wsl);
    cudaGetSymbolAddress(&pcnt, g_cnt);
    cudaGetSymbolAddress(&pstats, g_stats);
    cudaGetSymbolAddress(&ppooled, g_pooled);

    static cudaStream_t s2 = nullptr;
    static cudaEvent_t evA = nullptr, evB = nullptr;
    if (!s2) {
        cudaStreamCreateWithFlags(&s2, cudaStreamNonBlocking);
        cudaEventCreateWithFlags(&evA, cudaEventDisableTiming);
        cudaEventCreateWithFlags(&evB, cudaEventDisableTiming);
    }

    int nb = (N + 1023) / 1024;
    int gb = (N + 127) / 128;
    int gather_blocks = (int)(((long long)N * 32 + 255) / 256);
    int smem1 = 10240 * 4;     // single stage (GEMM4): 40960
    int smem2 = 20480 * 4;     // double-buffered (GEMM3): 81920
    int smem12 = 27648 * 4;    // fused GEMM1+2: 110592

    cudaFuncSetAttribute(gemm12_kernel,
                         cudaFuncAttributeMaxDynamicSharedMemorySize, smem12);
    cudaFuncSetAttribute(mma_gemm<128, 0, true, true, false>,
                         cudaFuncAttributeMaxDynamicSharedMemorySize, smem2);
    cudaFuncSetAttribute(mma_gemm<128, 2, false, false, true>,
                         cudaFuncAttributeMaxDynamicSharedMemorySize, smem1);

    // ---- fork: CSR build + gather_x on side stream ----
    cudaEventRecord(evA, 0);
    cudaStreamWaitEvent(s2, evA, 0);

    cudaMemsetAsync(pcnt, 0, (size_t)N * sizeof(int), s2);
    deg_kernel<<<(E + 255) / 256, 256, 0, s2>>>(dst, E);
    dinv_kernel<<<(N + 255) / 256, 256, 0, s2>>>(N);
    scan1_kernel<<<nb, 1024, 0, s2>>>(N);
    scan3_kernel<<<(N + 255) / 256, 256, 0, s2>>>(N);
    bin_kernel<<<(E + 255) / 256, 256, 0, s2>>>(src, dst, E);
    gatherx_kernel<<<gather_blocks, 256, 0, s2>>>(x, B2, N);   // Xs -> B2
    cudaEventRecord(evB, s2);

    // main stream: memsets + W pre-splits
    cudaMemsetAsync(pstats, 0, 2 * WN * sizeof(float));
    cudaMemsetAsync(ppooled, 0, (size_t)G * WN * sizeof(float));
    wsplit_kernel<<<8, 256>>>(W1, Wsh + 0, Wsl + 0, 32);
    wsplit_kernel<<<32, 256>>>(W2, Wsh + 8192, Wsl + 8192, 128);
    wsplit_kernel<<<32, 256>>>(W3, Wsh + 16384, Wsl + 16384, 128);
    wsplit_kernel<<<32, 256>>>(W4, Wsh + 24576, Wsl + 24576, 128);

    // join
    cudaStreamWaitEvent(0, evB, 0);

    // fused GEMM1+2: B0 = relu(Xs@W1 + b1) @ W2
    gemm12_kernel<<<gb, 256, smem12>>>(B2, Wsh, Wsl, Wsh + 8192, Wsl + 8192, b1, B0, N);

    // gather+relu -> split S1 (adds self + b2)
    gather_split_kernel<<<gather_blocks, 256>>>(B0, b2, S1h, S1l, N);

    // GEMM3 (pipelined): y = S1@W3 + b3 -> B1 (f32) + stats
    mma_gemm<128, 0, true, true, false><<<gb, 256, smem2>>>(
        nullptr, S1h, S1l, Wsh + 16384, Wsl + 16384, b3, B1, nullptr, nullptr, nullptr, N);

    // GEMM4: relu(bn(B1))@W4 + b4 (BN from g_stats in-kernel), fused max-pool
    mma_gemm<128, 2, false, false, true><<<gb, 256, smem1>>>(
        B1, nullptr, nullptr, Wsh + 24576, Wsl + 24576, b4, nullptr, g1, be1, bat, N);

    // final MLP
    final_kernel<<<1, 256>>>(W5, b5, g2, be2, W6, b6, (float*)d_out, G);
}

// round 15
// speedup vs baseline: 1.0793x; 1.0793x over previous
#include <cuda_runtime.h>

#define WN 128
#define NMAXN 100000
#define EMAX 600000
#define GMAX 64

// ---------------- scratch ----------------
__device__ float g_B0[(size_t)NMAXN * WN];
__device__ float g_B1[(size_t)NMAXN * WN];
__device__ float g_B2[(size_t)NMAXN * WN];
__device__ unsigned g_S1h[(size_t)NMAXN * 64];
__device__ unsigned g_S1l[(size_t)NMAXN * 64];
__device__ unsigned g_Wsh[4 * 8192];
__device__ unsigned g_Wsl[4 * 8192];
__device__ float g_dinv[NMAXN];
__device__ int   g_cnt[NMAXN];
__device__ int   g_rowtmp[NMAXN];
__device__ int   g_rowptr[NMAXN + 1];
__device__ int   g_cursor[NMAXN];
__device__ int   g_bsum[128];
__device__ int   g_boff[128];
__device__ int   g_scan_done;
__device__ int   g_pool_done;
__device__ int   g_csrc[EMAX];
__device__ float g_cdinv[EMAX];
__device__ float g_stats[2 * WN];
__device__ float g_pooled[GMAX * WN];

// ---------------- bf16 2-split helpers ----------------
__device__ __forceinline__ void split_bf16(float x, unsigned short& h, float& r) {
    asm("cvt.rn.bf16.f32 %0, %1;" : "=h"(h) : "f"(x));
    r = x - __uint_as_float(((unsigned)h) << 16);
}
__device__ __forceinline__ unsigned packf_bf16x2(float lo_, float hi_) {
    unsigned u;
    asm("cvt.rn.bf16x2.f32 %0, %1, %2;" : "=r"(u) : "f"(hi_), "f"(lo_));
    return u;
}
__device__ __forceinline__ void split_pair(float a, float b, unsigned& hi, unsigned& lo) {
    unsigned short ha, hb;
    float ra, rb;
    split_bf16(a, ha, ra);
    split_bf16(b, hb, rb);
    hi = ((unsigned)hb << 16) | (unsigned)ha;
    lo = packf_bf16x2(ra, rb);
}
__device__ __forceinline__ void mma_bf16(float* c, const unsigned* a, const unsigned* b) {
    asm volatile(
        "mma.sync.aligned.m16n8k16.row.col.f32.bf16.bf16.f32 "
        "{%0,%1,%2,%3}, {%4,%5,%6,%7}, {%8,%9}, {%0,%1,%2,%3};"
        : "+f"(c[0]), "+f"(c[1]), "+f"(c[2]), "+f"(c[3])
        : "r"(a[0]), "r"(a[1]), "r"(a[2]), "r"(a[3]), "r"(b[0]), "r"(b[1]));
}
__device__ __forceinline__ void cp16(unsigned* dst, const void* src, bool pred) {
    unsigned d = (unsigned)__cvta_generic_to_shared(dst);
    int sz = pred ? 16 : 0;
    asm volatile("cp.async.cg.shared.global [%0], [%1], 16, %2;"
                 :: "r"(d), "l"(src), "r"(sz));
}
__device__ __forceinline__ void cp_commit() {
    asm volatile("cp.async.commit_group;");
}
template<int NG>
__device__ __forceinline__ void cp_wait() {
    asm volatile("cp.async.wait_group %0;" :: "n"(NG));
}

// ---------------- degree / dinv ----------------
__global__ void deg_kernel(const int* __restrict__ dst, int E) {
    int e = blockIdx.x * blockDim.x + threadIdx.x;
    if (e < E) atomicAdd(&g_cnt[dst[e]], 1);
}

__global__ void dinv_kernel(int N) {
    int i = blockIdx.x * blockDim.x + threadIdx.x;
    if (i < N) g_dinv[i] = rsqrtf((float)g_cnt[i] + 1.0f);
}

// ---------------- CSR build: scan1 with fused last-block finalize ----------------
__global__ void scan1_kernel(int N) {
    __shared__ int sm[1024];
    __shared__ int isLast;
    int tid = threadIdx.x;
    int i = blockIdx.x * 1024 + tid;
    int v = (i < N) ? g_cnt[i] : 0;
    sm[tid] = v;
    __syncthreads();
#pragma unroll
    for (int o = 1; o < 1024; o <<= 1) {
        int t = 0;
        if (tid >= o) t = sm[tid - o];
        __syncthreads();
        if (tid >= o) sm[tid] += t;
        __syncthreads();
    }
    if (i < N) g_rowtmp[i] = sm[tid];
    if (tid == 1023) g_bsum[blockIdx.x] = sm[1023];
    __threadfence();
    if (tid == 0) isLast = (atomicAdd(&g_scan_done, 1) == (int)gridDim.x - 1);
    __syncthreads();
    if (isLast) {
        __shared__ int sm2[128];
        int nb = gridDim.x;
        int v2 = 0;
        if (tid < 128) {
            v2 = (tid < nb) ? g_bsum[tid] : 0;
            sm2[tid] = v2;
        }
        __syncthreads();
#pragma unroll
        for (int o = 1; o < 128; o <<= 1) {
            int u = 0;
            if (tid < 128 && tid >= o) u = sm2[tid - o];
            __syncthreads();
            if (tid < 128 && tid >= o) sm2[tid] += u;
            __syncthreads();
        }
        if (tid < 128 && tid < nb) g_boff[tid] = sm2[tid] - v2;
        if (tid == 127) g_rowptr[N] = sm2[127];
        if (tid == 0) g_scan_done = 0;
    }
}

__global__ void scan3_kernel(int N) {
    int i = blockIdx.x * blockDim.x + threadIdx.x;
    if (i < N) {
        int rp = g_rowtmp[i] - g_cnt[i] + g_boff[i >> 10];
        g_rowptr[i] = rp;
        g_cursor[i] = rp;
    }
}

__global__ void bin_kernel(const int* __restrict__ src, const int* __restrict__ dst, int E) {
    int e = blockIdx.x * blockDim.x + threadIdx.x;
    if (e >= E) return;
    int s = src[e], d = dst[e];
    int pos = atomicAdd(&g_cursor[d], 1);
    g_csrc[pos] = s;
    g_cdinv[pos] = g_dinv[s];
}

// ---------------- W split ----------------
__global__ void wsplit_kernel(const float* __restrict__ W, unsigned* __restrict__ oh,
                              unsigned* __restrict__ ol, int K) {
    int i = blockIdx.x * blockDim.x + threadIdx.x;
    int KP = K >> 1;
    if (i >= 128 * KP) return;
    int c = i / KP, kp = i % KP;
    unsigned h, l;
    split_pair(W[(size_t)(2 * kp) * WN + c], W[(size_t)(2 * kp + 1) * WN + c], h, l);
    oh[i] = h;
    ol[i] = l;
}

// ---------------- gather_x (32-wide) ----------------
__global__ void gatherx_kernel(const float* __restrict__ x, float* __restrict__ out, int N) {
    int t = blockIdx.x * blockDim.x + threadIdx.x;
    int w = t >> 5;
    if (w >= N) return;
    int lane = t & 31;
    int p0 = g_rowptr[w], p1 = g_rowptr[w + 1];
    float acc = 0.f;
    int e = p0;
    for (; e + 4 <= p1; e += 4) {
        int s0 = g_csrc[e], s1 = g_csrc[e + 1], s2 = g_csrc[e + 2], s3 = g_csrc[e + 3];
        float n0 = g_cdinv[e], n1 = g_cdinv[e + 1], n2 = g_cdinv[e + 2], n3 = g_cdinv[e + 3];
        acc = fmaf(x[(size_t)s0 * 32 + lane], n0, acc);
        acc = fmaf(x[(size_t)s1 * 32 + lane], n1, acc);
        acc = fmaf(x[(size_t)s2 * 32 + lane], n2, acc);
        acc = fmaf(x[(size_t)s3 * 32 + lane], n3, acc);
    }
    for (; e < p1; ++e)
        acc = fmaf(x[(size_t)g_csrc[e] * 32 + lane], g_cdinv[e], acc);
    float dv = g_dinv[w];
    out[(size_t)w * 32 + lane] = fmaf(acc, dv, x[(size_t)w * 32 + lane] * dv * dv);
}

// ---------------- gather -> split ----------------
__global__ void gather_split_kernel(const float* __restrict__ h, const float* __restrict__ bias,
                                    unsigned* __restrict__ oh, unsigned* __restrict__ ol, int N) {
    int t = blockIdx.x * blockDim.x + threadIdx.x;
    int w = t >> 5;
    if (w >= N) return;
    int lane = t & 31;
    int p0 = g_rowptr[w], p1 = g_rowptr[w + 1];
    float4 acc = make_float4(0.f, 0.f, 0.f, 0.f);
    int e = p0;
    for (; e + 4 <= p1; e += 4) {
        int s0 = g_csrc[e], s1 = g_csrc[e + 1], s2 = g_csrc[e + 2], s3 = g_csrc[e + 3];
        float n0 = g_cdinv[e], n1 = g_cdinv[e + 1], n2 = g_cdinv[e + 2], n3 = g_cdinv[e + 3];
        float4 v0 = ((const float4*)(h + (size_t)s0 * WN))[lane];
        float4 v1 = ((const float4*)(h + (size_t)s1 * WN))[lane];
        float4 v2 = ((const float4*)(h + (size_t)s2 * WN))[lane];
        float4 v3 = ((const float4*)(h + (size_t)s3 * WN))[lane];
        acc.x = fmaf(v0.x, n0, acc.x); acc.y = fmaf(v0.y, n0, acc.y);
        acc.z = fmaf(v0.z, n0, acc.z); acc.w = fmaf(v0.w, n0, acc.w);
        acc.x = fmaf(v1.x, n1, acc.x); acc.y = fmaf(v1.y, n1, acc.y);
        acc.z = fmaf(v1.z, n1, acc.z); acc.w = fmaf(v1.w, n1, acc.w);
        acc.x = fmaf(v2.x, n2, acc.x); acc.y = fmaf(v2.y, n2, acc.y);
        acc.z = fmaf(v2.z, n2, acc.z); acc.w = fmaf(v2.w, n2, acc.w);
        acc.x = fmaf(v3.x, n3, acc.x); acc.y = fmaf(v3.y, n3, acc.y);
        acc.z = fmaf(v3.z, n3, acc.z); acc.w = fmaf(v3.w, n3, acc.w);
    }
    for (; e < p1; ++e) {
        int s = g_csrc[e];
        float n = g_cdinv[e];
        float4 v = ((const float4*)(h + (size_t)s * WN))[lane];
        acc.x = fmaf(v.x, n, acc.x); acc.y = fmaf(v.y, n, acc.y);
        acc.z = fmaf(v.z, n, acc.z); acc.w = fmaf(v.w, n, acc.w);
    }
    float dv = g_dinv[w];
    float d2 = dv * dv;
    float4 hd = ((const float4*)(h + (size_t)w * WN))[lane];
    float4 b = ((const float4*)bias)[lane];
    float4 o;
    o.x = fmaxf(0.f, fmaf(acc.x, dv, fmaf(hd.x, d2, b.x)));
    o.y = fmaxf(0.f, fmaf(acc.y, dv, fmaf(hd.y, d2, b.y)));
    o.z = fmaxf(0.f, fmaf(acc.z, dv, fmaf(hd.z, d2, b.z)));
    o.w = fmaxf(0.f, fmaf(acc.w, dv, fmaf(hd.w, d2, b.w)));
    unsigned h0, l0, h1, l1;
    split_pair(o.x, o.y, h0, l0);
    split_pair(o.z, o.w, h1, l1);
    *(uint2*)&oh[(size_t)w * 64 + lane * 2] = make_uint2(h0, h1);
    *(uint2*)&ol[(size_t)w * 64 + lane * 2] = make_uint2(l0, l1);
}

// ---------------- fused GEMM1+GEMM2: B0 = relu(Xs@W1 + b1) @ W2 ----------------
__global__ __launch_bounds__(256, 2) void gemm12_kernel(
        const float* __restrict__ Xs,
        const unsigned* __restrict__ W1h, const unsigned* __restrict__ W1l,
        const unsigned* __restrict__ W2h, const unsigned* __restrict__ W2l,
        const float* __restrict__ b1, float* __restrict__ C, int M) {
    constexpr int ST = 20;
    constexpr int ST2 = 68;
    extern __shared__ unsigned smem[];
    unsigned* T1h = smem;                  // 8704
    unsigned* T1l = smem + 8704;
    unsigned* S   = smem + 17408;          // 10240

    int tid = threadIdx.x;
    int lane = tid & 31, wid = tid >> 5;
    int wm = wid >> 1, wn = wid & 1;
    int gr = lane >> 2;
    int row0 = blockIdx.x * 128;

    float acc[2][8][4];
#pragma unroll
    for (int mt = 0; mt < 2; ++mt)
#pragma unroll
        for (int nt = 0; nt < 8; ++nt)
#pragma unroll
            for (int q = 0; q < 4; ++q) acc[mt][nt][q] = 0.f;

    auto comp = [&](const unsigned* Ah, const unsigned* Al, int STa,
                    const unsigned* Wh, const unsigned* Wl) {
#pragma unroll
        for (int ks = 0; ks < 2; ++ks) {
            int kc = ks * 8 + (lane & 3);
            unsigned ah[2][4], al[2][4];
#pragma unroll
            for (int mt = 0; mt < 2; ++mt) {
                int r = wm * 32 + mt * 16 + gr;
                const unsigned* ph = &Ah[r * STa + kc];
                const unsigned* pl = &Al[r * STa + kc];
                ah[mt][0] = ph[0]; ah[mt][1] = ph[8 * STa];
                ah[mt][2] = ph[4]; ah[mt][3] = ph[8 * STa + 4];
                al[mt][0] = pl[0]; al[mt][1] = pl[8 * STa];
                al[mt][2] = pl[4]; al[mt][3] = pl[8 * STa + 4];
            }
#pragma unroll
            for (int nh = 0; nh < 2; ++nh) {
                unsigned bh[4][2], bl[4][2];
#pragma unroll
                for (int j = 0; j < 4; ++j) {
                    int c = wn * 64 + (nh * 4 + j) * 8 + gr;
                    bh[j][0] = Wh[c * ST + kc];
                    bh[j][1] = Wh[c * ST + kc + 4];
                    bl[j][0] = Wl[c * ST + kc];
                    bl[j][1] = Wl[c * ST + kc + 4];
                }
#pragma unroll
                for (int mt = 0; mt < 2; ++mt)
#pragma unroll
                    for (int j = 0; j < 4; ++j) {
                        float* cc = acc[mt][nh * 4 + j];
                        mma_bf16(cc, al[mt], bh[j]);
                        mma_bf16(cc, ah[mt], bl[j]);
                        mma_bf16(cc, ah[mt], bh[j]);
                    }
            }
        }
    };

    // ---- phase 1: T1 = relu(Xs@W1 + b1) ----
    {
        unsigned* Axh = S;
        unsigned* Axl = S + 2560;
        unsigned* W1s = S + 5120;
        unsigned* W1t = S + 7680;
        for (int i = tid; i < 512; i += 256) {
            int c = i >> 2, q = (i & 3) * 4;
            cp16(&W1s[c * ST + q], &W1h[(size_t)c * 16 + q], true);
            cp16(&W1t[c * ST + q], &W1l[(size_t)c * 16 + q], true);
        }
        cp_commit();
        for (int i = tid; i < 1024; i += 256) {
            int r = i >> 3, q = i & 7;
            float4 v = make_float4(0.f, 0.f, 0.f, 0.f);
            if (row0 + r < M)
                v = *(const float4*)(Xs + (size_t)(row0 + r) * 32 + 4 * q);
            unsigned h0, l0, h1, l1;
            split_pair(v.x, v.y, h0, l0);
            split_pair(v.z, v.w, h1, l1);
            *(uint2*)&Axh[r * ST + 2 * q] = make_uint2(h0, h1);
            *(uint2*)&Axl[r * ST + 2 * q] = make_uint2(l0, l1);
        }
        cp_wait<0>();
        __syncthreads();
        comp(Axh, Axl, ST, W1s, W1t);
        __syncthreads();
    }

    auto issueW2 = [&](int ci, int s) {
        unsigned* Wh = S + s * 5120;
        unsigned* Wl = Wh + 2560;
        int kp0 = ci * 16;
        for (int i = tid; i < 512; i += 256) {
            int c = i >> 2, q = (i & 3) * 4;
            cp16(&Wh[c * ST + q], &W2h[(size_t)c * 64 + kp0 + q], true);
            cp16(&Wl[c * ST + q], &W2l[(size_t)c * 64 + kp0 + q], true);
        }
        cp_commit();
    };
    issueW2(0, 0);
    issueW2(1, 1);

    // epilogue-1: relu(acc + b1) -> split T1; reset acc
    {
        float bv[16];
#pragma unroll
        for (int nt = 0; nt < 8; ++nt) {
            int col = wn * 64 + nt * 8 + (lane & 3) * 2;
            bv[nt * 2] = b1[col];
            bv[nt * 2 + 1] = b1[col + 1];
        }
#pragma unroll
        for (int mt = 0; mt < 2; ++mt)
#pragma unroll
            for (int h = 0; h < 2; ++h) {
                int r = wm * 32 + mt * 16 + gr + h * 8;
#pragma unroll
                for (int nt = 0; nt < 8; ++nt) {
                    int col = wn * 64 + nt * 8 + (lane & 3) * 2;
                    float v0 = fmaxf(0.f, acc[mt][nt][h * 2 + 0] + bv[nt * 2]);
                    float v1 = fmaxf(0.f, acc[mt][nt][h * 2 + 1] + bv[nt * 2 + 1]);
                    unsigned hh, ll;
                    split_pair(v0, v1, hh, ll);
                    T1h[r * ST2 + (col >> 1)] = hh;
                    T1l[r * ST2 + (col >> 1)] = ll;
                }
            }
#pragma unroll
        for (int mt = 0; mt < 2; ++mt)
#pragma unroll
            for (int nt = 0; nt < 8; ++nt)
#pragma unroll
                for (int q = 0; q < 4; ++q) acc[mt][nt][q] = 0.f;
    }
    __syncthreads();

    // ---- phase 2: B0 = T1 @ W2, 4 chunks; A base offset ci*16 kpairs ----
#pragma unroll
    for (int ci = 0; ci < 4; ++ci) {
        if (ci < 3) cp_wait<1>(); else cp_wait<0>();
        __syncthreads();
        comp(T1h + ci * 16, T1l + ci * 16, ST2,
             S + (ci & 1) * 5120, S + (ci & 1) * 5120 + 2560);
        __syncthreads();
        if (ci + 2 < 4) issueW2(ci + 2, ci & 1);
    }

    // epilogue-2: write f32
#pragma unroll
    for (int mt = 0; mt < 2; ++mt)
#pragma unroll
        for (int h = 0; h < 2; ++h) {
            int row = row0 + wm * 32 + mt * 16 + gr + h * 8;
            if (row >= M) continue;
#pragma unroll
            for (int nt = 0; nt < 8; ++nt) {
                int col = wn * 64 + nt * 8 + (lane & 3) * 2;
                *(float2*)(C + (size_t)row * WN + col) =
                    make_float2(acc[mt][nt][h * 2 + 0], acc[mt][nt][h * 2 + 1]);
            }
        }
}

// ---------------- 3x bf16-split tensor-core GEMM (GEMM3 / GEMM4) ----------------
// POOL: fused max-pool epilogue + last-CTA fused final MLP (writes fout).
template<int K, int PRO, bool INSPLIT, bool STATS, bool POOL>
__global__ __launch_bounds__(256, 2) void mma_gemm(
        const float* __restrict__ A,
        const unsigned* __restrict__ Agh, const unsigned* __restrict__ Agl,
        const unsigned* __restrict__ Wgh, const unsigned* __restrict__ Wgl,
        const float* __restrict__ bias, float* __restrict__ C,
        const float* __restrict__ bng, const float* __restrict__ bnb,
        const int* __restrict__ batch,
        const float* __restrict__ W5, const float* __restrict__ b5,
        const float* __restrict__ g2, const float* __restrict__ be2,
        const float* __restrict__ W6, const float* __restrict__ b6,
        float* __restrict__ fout, int Gn, int M) {
    constexpr int CH = 32;
    constexpr int KP = K / 2;
    constexpr int ST = 20;
    constexpr int NC = K / CH;
    constexpr int STAGE = 10240;
    extern __shared__ unsigned smem[];
    __shared__ float sstat[2 * WN];
    __shared__ float sbnp[2 * WN];

    int tid = threadIdx.x;
    int lane = tid & 31, wid = tid >> 5;
    int wm = wid >> 1, wn = wid & 1;
    int gr = lane >> 2;
    int row0 = blockIdx.x * 128;

    if (STATS) sstat[tid] = 0.f;
    if (PRO == 2) {
        if (tid < WN) {
            float inv = 1.0f / (float)M;
            float mu = g_stats[tid] * inv;
            float var = g_stats[WN + tid] * inv - mu * mu;
            float sc = bng[tid] * rsqrtf(var + 1e-5f);
            sbnp[tid] = sc;
            sbnp[WN + tid] = bnb[tid] - mu * sc;
        }
        __syncthreads();
    }

    float acc[2][8][4];
#pragma unroll
    for (int mt = 0; mt < 2; ++mt)
#pragma unroll
        for (int nt = 0; nt < 8; ++nt)
#pragma unroll
            for (int q = 0; q < 4; ++q) acc[mt][nt][q] = 0.f;

    auto compute = [&](const unsigned* Ah, const unsigned* Al,
                       const unsigned* Wh, const unsigned* Wl) {
#pragma unroll
        for (int ks = 0; ks < 2; ++ks) {
            int kc = ks * 8 + (lane & 3);
            unsigned ah[2][4], al[2][4];
#pragma unroll
            for (int mt = 0; mt < 2; ++mt) {
                int r = wm * 32 + mt * 16 + gr;
                const unsigned* ph = &Ah[r * ST + kc];
                const unsigned* pl = &Al[r * ST + kc];
                ah[mt][0] = ph[0]; ah[mt][1] = ph[8 * ST];
                ah[mt][2] = ph[4]; ah[mt][3] = ph[8 * ST + 4];
                al[mt][0] = pl[0]; al[mt][1] = pl[8 * ST];
                al[mt][2] = pl[4]; al[mt][3] = pl[8 * ST + 4];
            }
#pragma unroll
            for (int nh = 0; nh < 2; ++nh) {
                unsigned bh[4][2], bl[4][2];
#pragma unroll
                for (int j = 0; j < 4; ++j) {
                    int c = wn * 64 + (nh * 4 + j) * 8 + gr;
                    bh[j][0] = Wh[c * ST + kc];
                    bh[j][1] = Wh[c * ST + kc + 4];
                    bl[j][0] = Wl[c * ST + kc];
                    bl[j][1] = Wl[c * ST + kc + 4];
                }
#pragma unroll
                for (int mt = 0; mt < 2; ++mt)
#pragma unroll
                    for (int j = 0; j < 4; ++j) {
                        float* cc = acc[mt][nh * 4 + j];
                        mma_bf16(cc, al[mt], bh[j]);
                        mma_bf16(cc, ah[mt], bl[j]);
                        mma_bf16(cc, ah[mt], bh[j]);
                    }
            }
        }
    };

    if (INSPLIT) {
        auto issue = [&](int ci, int s) {
            unsigned* Ah = smem + s * STAGE;
            unsigned* Al = Ah + 2560;
            unsigned* Wh = Ah + 5120;
            unsigned* Wl = Ah + 7680;
            int kp0 = ci * (CH / 2);
#pragma unroll
            for (int i = tid; i < 512; i += 256) {
                int c = i >> 2, q = (i & 3) * 4;
                cp16(&Wh[c * ST + q], &Wgh[(size_t)c * KP + kp0 + q], true);
                cp16(&Wl[c * ST + q], &Wgl[(size_t)c * KP + kp0 + q], true);
            }
#pragma unroll
            for (int i = tid; i < 512; i += 256) {
                int r = i >> 2, q = (i & 3) * 4;
                bool ok = row0 + r < M;
                cp16(&Ah[r * ST + q], &Agh[(size_t)(row0 + r) * 64 + kp0 + q], ok);
                cp16(&Al[r * ST + q], &Agl[(size_t)(row0 + r) * 64 + kp0 + q], ok);
            }
            cp_commit();
        };
        issue(0, 0);
#pragma unroll
        for (int ci = 0; ci < NC; ++ci) {
            if (ci + 1 < NC) {
                issue(ci + 1, (ci + 1) & 1);
                cp_wait<1>();
            } else {
                cp_wait<0>();
            }
            __syncthreads();
            int s = ci & 1;
            compute(smem + s * STAGE, smem + s * STAGE + 2560,
                    smem + s * STAGE + 5120, smem + s * STAGE + 7680);
            __syncthreads();
        }
    } else {
        // A single buffer; W double-buffered via cp.async prefetch
        unsigned* Ah = smem;
        unsigned* Al = smem + 2560;
        auto issueW = [&](int ci, int s) {
            unsigned* Wh = smem + 5120 + s * 5120;
            unsigned* Wl = Wh + 2560;
            int kp0 = ci * (CH / 2);
#pragma unroll
            for (int i = tid; i < 512; i += 256) {
                int c = i >> 2, q = (i & 3) * 4;
                cp16(&Wh[c * ST + q], &Wgh[(size_t)c * KP + kp0 + q], true);
                cp16(&Wl[c * ST + q], &Wgl[(size_t)c * KP + kp0 + q], true);
            }
            cp_commit();
        };
        issueW(0, 0);
        for (int ci = 0; ci < NC; ++ci) {
            int kb = ci * CH;
            __syncthreads();   // previous compute done; A reusable
            if (ci + 1 < NC) issueW(ci + 1, (ci + 1) & 1);
            for (int i = tid; i < 128 * 8; i += 256) {
                int r = i >> 3, q = i & 7;
                float4 v = make_float4(0.f, 0.f, 0.f, 0.f);
                if (row0 + r < M)
                    v = *(const float4*)(A + (size_t)(row0 + r) * K + kb + 4 * q);
                if (PRO == 2) {
                    int kg = kb + 4 * q;
                    v.x = fmaxf(0.f, fmaf(v.x, sbnp[kg + 0], sbnp[WN + kg + 0]));
                    v.y = fmaxf(0.f, fmaf(v.y, sbnp[kg + 1], sbnp[WN + kg + 1]));
                    v.z = fmaxf(0.f, fmaf(v.z, sbnp[kg + 2], sbnp[WN + kg + 2]));
                    v.w = fmaxf(0.f, fmaf(v.w, sbnp[kg + 3], sbnp[WN + kg + 3]));
                }
                unsigned h0, l0, h1, l1;
                split_pair(v.x, v.y, h0, l0);
                split_pair(v.z, v.w, h1, l1);
                *(uint2*)&Ah[r * ST + 2 * q] = make_uint2(h0, h1);
                *(uint2*)&Al[r * ST + 2 * q] = make_uint2(l0, l1);
            }
            if (ci + 1 < NC) cp_wait<1>(); else cp_wait<0>();
            __syncthreads();
            unsigned* Wh = smem + 5120 + (ci & 1) * 5120;
            compute(Ah, Al, Wh, Wh + 2560);
        }
    }

    // ---------------- epilogue ----------------
    if (POOL) {
        int rbase = row0 + wm * 32 + gr;
        int bt[4];
#pragma unroll
        for (int t = 0; t < 4; ++t) {
            int r = rbase + t * 8;
            bt[t] = (r < M) ? batch[r] : -1;
        }
        bool same = (bt[0] == bt[1]) && (bt[1] == bt[2]) && (bt[2] == bt[3]) && (bt[0] >= 0);
#pragma unroll
        for (int nt = 0; nt < 8; ++nt) {
#pragma unroll
            for (int c = 0; c < 2; ++c) {
                int col = wn * 64 + nt * 8 + (lane & 3) * 2 + c;
                float bb = bias[col];
                float v[4];
                v[0] = fmaxf(0.f, acc[0][nt][c] + bb);
                v[1] = fmaxf(0.f, acc[0][nt][2 + c] + bb);
                v[2] = fmaxf(0.f, acc[1][nt][c] + bb);
                v[3] = fmaxf(0.f, acc[1][nt][2 + c] + bb);
                if (same) {
                    float m = fmaxf(fmaxf(v[0], v[1]), fmaxf(v[2], v[3]));
                    atomicMax((int*)&g_pooled[(size_t)bt[0] * WN + col], __float_as_int(m));
                } else {
#pragma unroll
                    for (int t = 0; t < 4; ++t)
                        if (bt[t] >= 0)
                            atomicMax((int*)&g_pooled[(size_t)bt[t] * WN + col],
                                      __float_as_int(v[t]));
                }
            }
        }

        // ---- fused final MLP: last CTA to finish pooling runs it ----
        __shared__ int lastf;
        __threadfence();
        if (tid == 0) lastf = (atomicAdd(&g_pool_done, 1) == (int)gridDim.x - 1);
        __syncthreads();
        if (!lastf) return;
        if (tid == 0) g_pool_done = 0;   // reset for graph replay

        __shared__ float ys[GMAX][65];
        __shared__ float fsc[64], fsh[64];
        float* W5s = (float*)smem;       // reuse dynamic smem (32 KB needed)
        for (int i = tid; i < WN * 64; i += 256) W5s[i] = W5[i];
        __syncthreads();

        int g = tid & 63;
        int jb = tid >> 6;
        float a2[16];
#pragma unroll
        for (int j = 0; j < 16; ++j) a2[j] = 0.f;
        if (g < Gn) {
            for (int k = 0; k < WN; ++k) {
                float p = g_pooled[(size_t)g * WN + k];
#pragma unroll
                for (int j = 0; j < 16; ++j)
                    a2[j] = fmaf(p, W5s[k * 64 + jb * 16 + j], a2[j]);
            }
#pragma unroll
            for (int j = 0; j < 16; ++j)
                ys[g][jb * 16 + j] = a2[j] + b5[jb * 16 + j];
        }
        __syncthreads();

        if (tid < 64) {
            float s = 0.f, q = 0.f;
            for (int r = 0; r < Gn; ++r) {
                float v = ys[r][tid];
                s += v;
                q += v * v;
            }
            float inv = 1.0f / (float)Gn;
            float mu = s * inv;
            float var = q * inv - mu * mu;
            float scale = g2[tid] * rsqrtf(var + 1e-5f);
            fsc[tid] = scale;
            fsh[tid] = be2[tid] - mu * scale;
        }
        __syncthreads();

        if (tid < Gn) {
            float o = b6[0];
            for (int j = 0; j < 64; ++j) {
                float v = fmaxf(0.f, fmaf(ys[tid][j], fsc[j], fsh[j]));
                o = fmaf(v, W6[j], o);
            }
            fout[tid] = o;
        }
        return;
    }

    float ss[16], sq[16];
    if (STATS) {
#pragma unroll
        for (int i = 0; i < 16; ++i) { ss[i] = 0.f; sq[i] = 0.f; }
    }

#pragma unroll
    for (int mt = 0; mt < 2; ++mt) {
#pragma unroll
        for (int h = 0; h < 2; ++h) {
            int row = row0 + wm * 32 + mt * 16 + gr + h * 8;
            bool ok = row < M;
#pragma unroll
            for (int nt = 0; nt < 8; ++nt) {
                int col = wn * 64 + nt * 8 + (lane & 3) * 2;
                float b0 = bias ? bias[col] : 0.f;
                float b1 = bias ? bias[col + 1] : 0.f;
                float o0 = acc[mt][nt][h * 2 + 0] + b0;
                float o1 = acc[mt][nt][h * 2 + 1] + b1;
                if (ok)
                    *(float2*)(C + (size_t)row * WN + col) = make_float2(o0, o1);
                if (STATS) {
                    if (!ok) { o0 = 0.f; o1 = 0.f; }
                    ss[nt * 2 + 0] += o0; sq[nt * 2 + 0] += o0 * o0;
                    ss[nt * 2 + 1] += o1; sq[nt * 2 + 1] += o1 * o1;
                }
            }
        }
    }

    if (STATS) {
#pragma unroll
        for (int i = 0; i < 16; ++i) {
#pragma unroll
            for (int o = 4; o <= 16; o <<= 1) {
                ss[i] += __shfl_xor_sync(0xffffffffu, ss[i], o);
                sq[i] += __shfl_xor_sync(0xffffffffu, sq[i], o);
            }
        }
        if (lane < 4) {
#pragma unroll
            for (int nt = 0; nt < 8; ++nt)
#pragma unroll
                for (int c = 0; c < 2; ++c) {
                    int col = wn * 64 + nt * 8 + lane * 2 + c;
                    atomicAdd(&sstat[col], ss[nt * 2 + c]);
                    atomicAdd(&sstat[WN + col], sq[nt * 2 + c]);
                }
        }
        __syncthreads();
        atomicAdd(&g_stats[tid], sstat[tid]);
    }
}

// ---------------- launch ----------------
extern "C" void kernel_launch(void* const* d_in, const int* in_sizes, int n_in,
                              void* d_out, int out_size) {
    const float* x   = (const float*)d_in[0];
    const int*   ei  = (const int*)d_in[1];
    const int*   bat = (const int*)d_in[2];
    const float* W1  = (const float*)d_in[3];
    const float* b1  = (const float*)d_in[4];
    const float* W2  = (const float*)d_in[5];
    const float* b2  = (const float*)d_in[6];
    const float* W3  = (const float*)d_in[7];
    const float* b3  = (const float*)d_in[8];
    const float* g1  = (const float*)d_in[9];
    const float* be1 = (const float*)d_in[10];
    const float* W4  = (const float*)d_in[11];
    const float* b4  = (const float*)d_in[12];
    const float* W5  = (const float*)d_in[13];
    const float* b5  = (const float*)d_in[14];
    const float* g2  = (const float*)d_in[15];
    const float* be2 = (const float*)d_in[16];
    const float* W6  = (const float*)d_in[17];
    const float* b6  = (const float*)d_in[18];

    int N = in_sizes[2];
    int E = in_sizes[1] / 2;
    int G = out_size;
    const int* src = ei;
    const int* dst = ei + E;

    float *B0, *B1, *B2;
    unsigned *S1h, *S1l, *Wsh, *Wsl;
    void *pcnt, *pstats, *ppooled;
    cudaGetSymbolAddress((void**)&B0, g_B0);
    cudaGetSymbolAddress((void**)&B1, g_B1);
    cudaGetSymbolAddress((void**)&B2, g_B2);
    cudaGetSymbolAddress((void**)&S1h, g_S1h);
    cudaGetSymbolAddress((void**)&S1l, g_S1l);
    cudaGetSymbolAddress((void**)&Wsh, g_Wsh);
    cudaGetSymbolAddress((void**)&Wsl, g_Wsl);
    cudaGetSymbolAddress(&pcnt, g_cnt);
    cudaGetSymbolAddress(&pstats, g_stats);
    cudaGetSymbolAddress(&ppooled, g_pooled);

    static cudaStream_t s2 = nullptr;
    static cudaEvent_t evA = nullptr, evB = nullptr;
    if (!s2) {
        cudaStreamCreateWithFlags(&s2, cudaStreamNonBlocking);
        cudaEventCreateWithFlags(&evA, cudaEventDisableTiming);
        cudaEventCreateWithFlags(&evB, cudaEventDisableTiming);
    }

    int nb = (N + 1023) / 1024;
    int gb = (N + 127) / 128;
    int gather_blocks = (int)(((long long)N * 32 + 255) / 256);
    int smem1 = 15360 * 4;     // GEMM4: A single + W double-buffer = 61440
    int smem2 = 20480 * 4;     // GEMM3 double-buffered: 81920
    int smem12 = 27648 * 4;    // fused GEMM1+2: 110592

    cudaFuncSetAttribute(gemm12_kernel,
                         cudaFuncAttributeMaxDynamicSharedMemorySize, smem12);
    cudaFuncSetAttribute(mma_gemm<128, 0, true, true, false>,
                         cudaFuncAttributeMaxDynamicSharedMemorySize, smem2);
    cudaFuncSetAttribute(mma_gemm<128, 2, false, false, true>,
                         cudaFuncAttributeMaxDynamicSharedMemorySize, smem1);

    // ---- fork: CSR build + gather_x on side stream ----
    cudaEventRecord(evA, 0);
    cudaStreamWaitEvent(s2, evA, 0);

    cudaMemsetAsync(pcnt, 0, (size_t)N * sizeof(int), s2);
    deg_kernel<<<(E + 255) / 256, 256, 0, s2>>>(dst, E);
    dinv_kernel<<<(N + 255) / 256, 256, 0, s2>>>(N);
    scan1_kernel<<<nb, 1024, 0, s2>>>(N);
    scan3_kernel<<<(N + 255) / 256, 256, 0, s2>>>(N);
    bin_kernel<<<(E + 255) / 256, 256, 0, s2>>>(src, dst, E);
    gatherx_kernel<<<gather_blocks, 256, 0, s2>>>(x, B2, N);   // Xs -> B2
    cudaEventRecord(evB, s2);

    // main stream: memsets + W pre-splits
    cudaMemsetAsync(pstats, 0, 2 * WN * sizeof(float));
    cudaMemsetAsync(ppooled, 0, (size_t)G * WN * sizeof(float));
    wsplit_kernel<<<8, 256>>>(W1, Wsh + 0, Wsl + 0, 32);
    wsplit_kernel<<<32, 256>>>(W2, Wsh + 8192, Wsl + 8192, 128);
    wsplit_kernel<<<32, 256>>>(W3, Wsh + 16384, Wsl + 16384, 128);
    wsplit_kernel<<<32, 256>>>(W4, Wsh + 24576, Wsl + 24576, 128);

    // join
    cudaStreamWaitEvent(0, evB, 0);

    // fused GEMM1+2: B0 = relu(Xs@W1 + b1) @ W2
    gemm12_kernel<<<gb, 256, smem12>>>(B2, Wsh, Wsl, Wsh + 8192, Wsl + 8192, b1, B0, N);

    // gather+relu -> split S1 (adds self + b2)
    gather_split_kernel<<<gather_blocks, 256>>>(B0, b2, S1h, S1l, N);

    // GEMM3 (pipelined): y = S1@W3 + b3 -> B1 (f32) + stats
    mma_gemm<128, 0, true, true, false><<<gb, 256, smem2>>>(
        nullptr, S1h, S1l, Wsh + 16384, Wsl + 16384, b3, B1, nullptr, nullptr, nullptr,
        nullptr, nullptr, nullptr, nullptr, nullptr, nullptr, nullptr, G, N);

    // GEMM4: relu(bn(B1))@W4 + b4, fused max-pool + last-CTA final MLP -> d_out
    mma_gemm<128, 2, false, false, true><<<gb, 256, smem1>>>(
        B1, nullptr, nullptr, Wsh + 24576, Wsl + 24576, b4, nullptr, g1, be1, bat,
        W5, b5, g2, be2, W6, b6, (float*)d_out, G, N);
}

// round 16
// speedup vs baseline: 1.0855x; 1.0058x over previous
#include <cuda_runtime.h>

#define WN 128
#define NMAXN 100000
#define EMAX 600000
#define GMAX 64

// ---------------- scratch ----------------
__device__ float g_B0[(size_t)NMAXN * WN];
__device__ float g_B1[(size_t)NMAXN * WN];
__device__ float g_B2[(size_t)NMAXN * WN];
__device__ unsigned g_S1h[(size_t)NMAXN * 64];
__device__ unsigned g_S1l[(size_t)NMAXN * 64];
__device__ unsigned g_Wsh[4 * 8192];
__device__ unsigned g_Wsl[4 * 8192];
__device__ float g_dinv[NMAXN];
__device__ int   g_cnt[NMAXN];
__device__ int   g_rowtmp[NMAXN];
__device__ int   g_rowptr[NMAXN + 1];
__device__ int   g_cursor[NMAXN];
__device__ int   g_bsum[128];
__device__ int   g_boff[128];
__device__ int   g_scan_done;
__device__ int   g_pool_done;
__device__ int   g_csrc[EMAX];
__device__ float g_cdinv[EMAX];
__device__ float g_stats[2 * WN];
__device__ float g_pooled[GMAX * WN];

// ---------------- bf16 2-split helpers ----------------
__device__ __forceinline__ void split_bf16(float x, unsigned short& h, float& r) {
    asm("cvt.rn.bf16.f32 %0, %1;" : "=h"(h) : "f"(x));
    r = x - __uint_as_float(((unsigned)h) << 16);
}
__device__ __forceinline__ unsigned packf_bf16x2(float lo_, float hi_) {
    unsigned u;
    asm("cvt.rn.bf16x2.f32 %0, %1, %2;" : "=r"(u) : "f"(hi_), "f"(lo_));
    return u;
}
__device__ __forceinline__ void split_pair(float a, float b, unsigned& hi, unsigned& lo) {
    unsigned short ha, hb;
    float ra, rb;
    split_bf16(a, ha, ra);
    split_bf16(b, hb, rb);
    hi = ((unsigned)hb << 16) | (unsigned)ha;
    lo = packf_bf16x2(ra, rb);
}
__device__ __forceinline__ void mma_bf16(float* c, const unsigned* a, const unsigned* b) {
    asm volatile(
        "mma.sync.aligned.m16n8k16.row.col.f32.bf16.bf16.f32 "
        "{%0,%1,%2,%3}, {%4,%5,%6,%7}, {%8,%9}, {%0,%1,%2,%3};"
        : "+f"(c[0]), "+f"(c[1]), "+f"(c[2]), "+f"(c[3])
        : "r"(a[0]), "r"(a[1]), "r"(a[2]), "r"(a[3]), "r"(b[0]), "r"(b[1]));
}
__device__ __forceinline__ void cp16(unsigned* dst, const void* src, bool pred) {
    unsigned d = (unsigned)__cvta_generic_to_shared(dst);
    int sz = pred ? 16 : 0;
    asm volatile("cp.async.cg.shared.global [%0], [%1], 16, %2;"
                 :: "r"(d), "l"(src), "r"(sz));
}
__device__ __forceinline__ void cp_commit() {
    asm volatile("cp.async.commit_group;");
}
template<int NG>
__device__ __forceinline__ void cp_wait() {
    asm volatile("cp.async.wait_group %0;" :: "n"(NG));
}

// ---------------- degree / dinv ----------------
__global__ void deg_kernel(const int* __restrict__ dst, int E) {
    int e = blockIdx.x * blockDim.x + threadIdx.x;
    if (e < E) atomicAdd(&g_cnt[dst[e]], 1);
}

__global__ void dinv_kernel(int N) {
    int i = blockIdx.x * blockDim.x + threadIdx.x;
    if (i < N) g_dinv[i] = rsqrtf((float)g_cnt[i] + 1.0f);
}

// ---------------- CSR build: scan1 with fused last-block finalize ----------------
__global__ void scan1_kernel(int N) {
    __shared__ int sm[1024];
    __shared__ int isLast;
    int tid = threadIdx.x;
    int i = blockIdx.x * 1024 + tid;
    int v = (i < N) ? g_cnt[i] : 0;
    sm[tid] = v;
    __syncthreads();
#pragma unroll
    for (int o = 1; o < 1024; o <<= 1) {
        int t = 0;
        if (tid >= o) t = sm[tid - o];
        __syncthreads();
        if (tid >= o) sm[tid] += t;
        __syncthreads();
    }
    if (i < N) g_rowtmp[i] = sm[tid];
    if (tid == 1023) g_bsum[blockIdx.x] = sm[1023];
    __threadfence();
    if (tid == 0) isLast = (atomicAdd(&g_scan_done, 1) == (int)gridDim.x - 1);
    __syncthreads();
    if (isLast) {
        __shared__ int sm2[128];
        int nb = gridDim.x;
        int v2 = 0;
        if (tid < 128) {
            v2 = (tid < nb) ? g_bsum[tid] : 0;
            sm2[tid] = v2;
        }
        __syncthreads();
#pragma unroll
        for (int o = 1; o < 128; o <<= 1) {
            int u = 0;
            if (tid < 128 && tid >= o) u = sm2[tid - o];
            __syncthreads();
            if (tid < 128 && tid >= o) sm2[tid] += u;
            __syncthreads();
        }
        if (tid < 128 && tid < nb) g_boff[tid] = sm2[tid] - v2;
        if (tid == 127) g_rowptr[N] = sm2[127];
        if (tid == 0) g_scan_done = 0;
    }
}

__global__ void scan3_kernel(int N) {
    int i = blockIdx.x * blockDim.x + threadIdx.x;
    if (i < N) {
        int rp = g_rowtmp[i] - g_cnt[i] + g_boff[i >> 10];
        g_rowptr[i] = rp;
        g_cursor[i] = rp;
    }
}

__global__ void bin_kernel(const int* __restrict__ src, const int* __restrict__ dst, int E) {
    int e = blockIdx.x * blockDim.x + threadIdx.x;
    if (e >= E) return;
    int s = src[e], d = dst[e];
    int pos = atomicAdd(&g_cursor[d], 1);
    g_csrc[pos] = s;
    g_cdinv[pos] = g_dinv[s];
}

// ---------------- W split ----------------
__global__ void wsplit_kernel(const float* __restrict__ W, unsigned* __restrict__ oh,
                              unsigned* __restrict__ ol, int K) {
    int i = blockIdx.x * blockDim.x + threadIdx.x;
    int KP = K >> 1;
    if (i >= 128 * KP) return;
    int c = i / KP, kp = i % KP;
    unsigned h, l;
    split_pair(W[(size_t)(2 * kp) * WN + c], W[(size_t)(2 * kp + 1) * WN + c], h, l);
    oh[i] = h;
    ol[i] = l;
}

// ---------------- gather_x (32-wide) ----------------
__global__ void gatherx_kernel(const float* __restrict__ x, float* __restrict__ out, int N) {
    int t = blockIdx.x * blockDim.x + threadIdx.x;
    int w = t >> 5;
    if (w >= N) return;
    int lane = t & 31;
    int p0 = g_rowptr[w], p1 = g_rowptr[w + 1];
    float acc = 0.f;
    int e = p0;
    for (; e + 4 <= p1; e += 4) {
        int s0 = g_csrc[e], s1 = g_csrc[e + 1], s2 = g_csrc[e + 2], s3 = g_csrc[e + 3];
        float n0 = g_cdinv[e], n1 = g_cdinv[e + 1], n2 = g_cdinv[e + 2], n3 = g_cdinv[e + 3];
        acc = fmaf(x[(size_t)s0 * 32 + lane], n0, acc);
        acc = fmaf(x[(size_t)s1 * 32 + lane], n1, acc);
        acc = fmaf(x[(size_t)s2 * 32 + lane], n2, acc);
        acc = fmaf(x[(size_t)s3 * 32 + lane], n3, acc);
    }
    for (; e < p1; ++e)
        acc = fmaf(x[(size_t)g_csrc[e] * 32 + lane], g_cdinv[e], acc);
    float dv = g_dinv[w];
    out[(size_t)w * 32 + lane] = fmaf(acc, dv, x[(size_t)w * 32 + lane] * dv * dv);
}

// ---------------- gather -> split ----------------
__global__ void gather_split_kernel(const float* __restrict__ h, const float* __restrict__ bias,
                                    unsigned* __restrict__ oh, unsigned* __restrict__ ol, int N) {
    int t = blockIdx.x * blockDim.x + threadIdx.x;
    int w = t >> 5;
    if (w >= N) return;
    int lane = t & 31;
    int p0 = g_rowptr[w], p1 = g_rowptr[w + 1];
    float4 acc = make_float4(0.f, 0.f, 0.f, 0.f);
    int e = p0;
    for (; e + 4 <= p1; e += 4) {
        int s0 = g_csrc[e], s1 = g_csrc[e + 1], s2 = g_csrc[e + 2], s3 = g_csrc[e + 3];
        float n0 = g_cdinv[e], n1 = g_cdinv[e + 1], n2 = g_cdinv[e + 2], n3 = g_cdinv[e + 3];
        float4 v0 = ((const float4*)(h + (size_t)s0 * WN))[lane];
        float4 v1 = ((const float4*)(h + (size_t)s1 * WN))[lane];
        float4 v2 = ((const float4*)(h + (size_t)s2 * WN))[lane];
        float4 v3 = ((const float4*)(h + (size_t)s3 * WN))[lane];
        acc.x = fmaf(v0.x, n0, acc.x); acc.y = fmaf(v0.y, n0, acc.y);
        acc.z = fmaf(v0.z, n0, acc.z); acc.w = fmaf(v0.w, n0, acc.w);
        acc.x = fmaf(v1.x, n1, acc.x); acc.y = fmaf(v1.y, n1, acc.y);
        acc.z = fmaf(v1.z, n1, acc.z); acc.w = fmaf(v1.w, n1, acc.w);
        acc.x = fmaf(v2.x, n2, acc.x); acc.y = fmaf(v2.y, n2, acc.y);
        acc.z = fmaf(v2.z, n2, acc.z); acc.w = fmaf(v2.w, n2, acc.w);
        acc.x = fmaf(v3.x, n3, acc.x); acc.y = fmaf(v3.y, n3, acc.y);
        acc.z = fmaf(v3.z, n3, acc.z); acc.w = fmaf(v3.w, n3, acc.w);
    }
    for (; e < p1; ++e) {
        int s = g_csrc[e];
        float n = g_cdinv[e];
        float4 v = ((const float4*)(h + (size_t)s * WN))[lane];
        acc.x = fmaf(v.x, n, acc.x); acc.y = fmaf(v.y, n, acc.y);
        acc.z = fmaf(v.z, n, acc.z); acc.w = fmaf(v.w, n, acc.w);
    }
    float dv = g_dinv[w];
    float d2 = dv * dv;
    float4 hd = ((const float4*)(h + (size_t)w * WN))[lane];
    float4 b = ((const float4*)bias)[lane];
    float4 o;
    o.x = fmaxf(0.f, fmaf(acc.x, dv, fmaf(hd.x, d2, b.x)));
    o.y = fmaxf(0.f, fmaf(acc.y, dv, fmaf(hd.y, d2, b.y)));
    o.z = fmaxf(0.f, fmaf(acc.z, dv, fmaf(hd.z, d2, b.z)));
    o.w = fmaxf(0.f, fmaf(acc.w, dv, fmaf(hd.w, d2, b.w)));
    unsigned h0, l0, h1, l1;
    split_pair(o.x, o.y, h0, l0);
    split_pair(o.z, o.w, h1, l1);
    *(uint2*)&oh[(size_t)w * 64 + lane * 2] = make_uint2(h0, h1);
    *(uint2*)&ol[(size_t)w * 64 + lane * 2] = make_uint2(l0, l1);
}

// ---------------- fused GEMM1+GEMM2: B0 = relu(Xs@W1 + b1) @ W2 ----------------
__global__ __launch_bounds__(256, 2) void gemm12_kernel(
        const float* __restrict__ Xs,
        const unsigned* __restrict__ W1h, const unsigned* __restrict__ W1l,
        const unsigned* __restrict__ W2h, const unsigned* __restrict__ W2l,
        const float* __restrict__ b1, float* __restrict__ C, int M) {
    constexpr int ST = 20;
    constexpr int ST2 = 68;
    extern __shared__ unsigned smem[];
    unsigned* T1h = smem;                  // 8704
    unsigned* T1l = smem + 8704;
    unsigned* S   = smem + 17408;          // 10240

    int tid = threadIdx.x;
    int lane = tid & 31, wid = tid >> 5;
    int wm = wid >> 1, wn = wid & 1;
    int gr = lane >> 2;
    int row0 = blockIdx.x * 128;

    float acc[2][8][4];
#pragma unroll
    for (int mt = 0; mt < 2; ++mt)
#pragma unroll
        for (int nt = 0; nt < 8; ++nt)
#pragma unroll
            for (int q = 0; q < 4; ++q) acc[mt][nt][q] = 0.f;

    auto comp = [&](const unsigned* Ah, const unsigned* Al, int STa,
                    const unsigned* Wh, const unsigned* Wl) {
#pragma unroll
        for (int ks = 0; ks < 2; ++ks) {
            int kc = ks * 8 + (lane & 3);
            unsigned ah[2][4], al[2][4];
#pragma unroll
            for (int mt = 0; mt < 2; ++mt) {
                int r = wm * 32 + mt * 16 + gr;
                const unsigned* ph = &Ah[r * STa + kc];
                const unsigned* pl = &Al[r * STa + kc];
                ah[mt][0] = ph[0]; ah[mt][1] = ph[8 * STa];
                ah[mt][2] = ph[4]; ah[mt][3] = ph[8 * STa + 4];
                al[mt][0] = pl[0]; al[mt][1] = pl[8 * STa];
                al[mt][2] = pl[4]; al[mt][3] = pl[8 * STa + 4];
            }
#pragma unroll
            for (int nh = 0; nh < 2; ++nh) {
                unsigned bh[4][2], bl[4][2];
#pragma unroll
                for (int j = 0; j < 4; ++j) {
                    int c = wn * 64 + (nh * 4 + j) * 8 + gr;
                    bh[j][0] = Wh[c * ST + kc];
                    bh[j][1] = Wh[c * ST + kc + 4];
                    bl[j][0] = Wl[c * ST + kc];
                    bl[j][1] = Wl[c * ST + kc + 4];
                }
#pragma unroll
                for (int mt = 0; mt < 2; ++mt)
#pragma unroll
                    for (int j = 0; j < 4; ++j) {
                        float* cc = acc[mt][nh * 4 + j];
                        mma_bf16(cc, al[mt], bh[j]);
                        mma_bf16(cc, ah[mt], bl[j]);
                        mma_bf16(cc, ah[mt], bh[j]);
                    }
            }
        }
    };

    // ---- phase 1: T1 = relu(Xs@W1 + b1) ----
    {
        unsigned* Axh = S;
        unsigned* Axl = S + 2560;
        unsigned* W1s = S + 5120;
        unsigned* W1t = S + 7680;
        for (int i = tid; i < 512; i += 256) {
            int c = i >> 2, q = (i & 3) * 4;
            cp16(&W1s[c * ST + q], &W1h[(size_t)c * 16 + q], true);
            cp16(&W1t[c * ST + q], &W1l[(size_t)c * 16 + q], true);
        }
        cp_commit();
        for (int i = tid; i < 1024; i += 256) {
            int r = i >> 3, q = i & 7;
            float4 v = make_float4(0.f, 0.f, 0.f, 0.f);
            if (row0 + r < M)
                v = *(const float4*)(Xs + (size_t)(row0 + r) * 32 + 4 * q);
            unsigned h0, l0, h1, l1;
            split_pair(v.x, v.y, h0, l0);
            split_pair(v.z, v.w, h1, l1);
            *(uint2*)&Axh[r * ST + 2 * q] = make_uint2(h0, h1);
            *(uint2*)&Axl[r * ST + 2 * q] = make_uint2(l0, l1);
        }
        cp_wait<0>();
        __syncthreads();
        comp(Axh, Axl, ST, W1s, W1t);
        __syncthreads();
    }

    auto issueW2 = [&](int ci, int s) {
        unsigned* Wh = S + s * 5120;
        unsigned* Wl = Wh + 2560;
        int kp0 = ci * 16;
        for (int i = tid; i < 512; i += 256) {
            int c = i >> 2, q = (i & 3) * 4;
            cp16(&Wh[c * ST + q], &W2h[(size_t)c * 64 + kp0 + q], true);
            cp16(&Wl[c * ST + q], &W2l[(size_t)c * 64 + kp0 + q], true);
        }
        cp_commit();
    };
    issueW2(0, 0);
    issueW2(1, 1);

    // epilogue-1: relu(acc + b1) -> split T1; reset acc
    {
        float bv[16];
#pragma unroll
        for (int nt = 0; nt < 8; ++nt) {
            int col = wn * 64 + nt * 8 + (lane & 3) * 2;
            bv[nt * 2] = b1[col];
            bv[nt * 2 + 1] = b1[col + 1];
        }
#pragma unroll
        for (int mt = 0; mt < 2; ++mt)
#pragma unroll
            for (int h = 0; h < 2; ++h) {
                int r = wm * 32 + mt * 16 + gr + h * 8;
#pragma unroll
                for (int nt = 0; nt < 8; ++nt) {
                    int col = wn * 64 + nt * 8 + (lane & 3) * 2;
                    float v0 = fmaxf(0.f, acc[mt][nt][h * 2 + 0] + bv[nt * 2]);
                    float v1 = fmaxf(0.f, acc[mt][nt][h * 2 + 1] + bv[nt * 2 + 1]);
                    unsigned hh, ll;
                    split_pair(v0, v1, hh, ll);
                    T1h[r * ST2 + (col >> 1)] = hh;
                    T1l[r * ST2 + (col >> 1)] = ll;
                }
            }
#pragma unroll
        for (int mt = 0; mt < 2; ++mt)
#pragma unroll
            for (int nt = 0; nt < 8; ++nt)
#pragma unroll
                for (int q = 0; q < 4; ++q) acc[mt][nt][q] = 0.f;
    }
    __syncthreads();

    // ---- phase 2: B0 = T1 @ W2, 4 chunks; A base offset ci*16 kpairs ----
#pragma unroll
    for (int ci = 0; ci < 4; ++ci) {
        if (ci < 3) cp_wait<1>(); else cp_wait<0>();
        __syncthreads();
        comp(T1h + ci * 16, T1l + ci * 16, ST2,
             S + (ci & 1) * 5120, S + (ci & 1) * 5120 + 2560);
        __syncthreads();
        if (ci + 2 < 4) issueW2(ci + 2, ci & 1);
    }

    // epilogue-2: write f32
#pragma unroll
    for (int mt = 0; mt < 2; ++mt)
#pragma unroll
        for (int h = 0; h < 2; ++h) {
            int row = row0 + wm * 32 + mt * 16 + gr + h * 8;
            if (row >= M) continue;
#pragma unroll
            for (int nt = 0; nt < 8; ++nt) {
                int col = wn * 64 + nt * 8 + (lane & 3) * 2;
                *(float2*)(C + (size_t)row * WN + col) =
                    make_float2(acc[mt][nt][h * 2 + 0], acc[mt][nt][h * 2 + 1]);
            }
        }
}

// ---------------- 3x bf16-split tensor-core GEMM (GEMM3 / GEMM4) ----------------
// POOL: fused max-pool epilogue + last-CTA fused final MLP (writes fout).
template<int K, int PRO, bool INSPLIT, bool STATS, bool POOL>
__global__ __launch_bounds__(256, 2) void mma_gemm(
        const float* __restrict__ A,
        const unsigned* __restrict__ Agh, const unsigned* __restrict__ Agl,
        const unsigned* __restrict__ Wgh, const unsigned* __restrict__ Wgl,
        const float* __restrict__ bias, float* __restrict__ C,
        const float* __restrict__ bng, const float* __restrict__ bnb,
        const int* __restrict__ batch,
        const float* __restrict__ W5, const float* __restrict__ b5,
        const float* __restrict__ g2, const float* __restrict__ be2,
        const float* __restrict__ W6, const float* __restrict__ b6,
        float* __restrict__ fout, int Gn, int M) {
    constexpr int CH = 32;
    constexpr int KP = K / 2;
    constexpr int ST = 20;
    constexpr int NC = K / CH;
    constexpr int STAGE = 10240;
    extern __shared__ unsigned smem[];
    __shared__ float sstat[2 * WN];
    __shared__ float sbnp[2 * WN];

    int tid = threadIdx.x;
    int lane = tid & 31, wid = tid >> 5;
    int wm = wid >> 1, wn = wid & 1;
    int gr = lane >> 2;
    int row0 = blockIdx.x * 128;

    if (STATS) sstat[tid] = 0.f;
    if (PRO == 2) {
        if (tid < WN) {
            float inv = 1.0f / (float)M;
            float mu = g_stats[tid] * inv;
            float var = g_stats[WN + tid] * inv - mu * mu;
            float sc = bng[tid] * rsqrtf(var + 1e-5f);
            sbnp[tid] = sc;
            sbnp[WN + tid] = bnb[tid] - mu * sc;
        }
        __syncthreads();
    }

    float acc[2][8][4];
#pragma unroll
    for (int mt = 0; mt < 2; ++mt)
#pragma unroll
        for (int nt = 0; nt < 8; ++nt)
#pragma unroll
            for (int q = 0; q < 4; ++q) acc[mt][nt][q] = 0.f;

    auto issue = [&](int ci, int s) {
        unsigned* Ah = smem + s * STAGE;
        unsigned* Al = Ah + 2560;
        unsigned* Wh = Ah + 5120;
        unsigned* Wl = Ah + 7680;
        int kp0 = ci * (CH / 2);
#pragma unroll
        for (int i = tid; i < 512; i += 256) {
            int c = i >> 2, q = (i & 3) * 4;
            cp16(&Wh[c * ST + q], &Wgh[(size_t)c * KP + kp0 + q], true);
            cp16(&Wl[c * ST + q], &Wgl[(size_t)c * KP + kp0 + q], true);
        }
#pragma unroll
        for (int i = tid; i < 512; i += 256) {
            int r = i >> 2, q = (i & 3) * 4;
            bool ok = row0 + r < M;
            cp16(&Ah[r * ST + q], &Agh[(size_t)(row0 + r) * 64 + kp0 + q], ok);
            cp16(&Al[r * ST + q], &Agl[(size_t)(row0 + r) * 64 + kp0 + q], ok);
        }
        cp_commit();
    };

    auto compute = [&](int s) {
        unsigned* Ah = smem + s * STAGE;
        unsigned* Al = Ah + 2560;
        unsigned* Wh = Ah + 5120;
        unsigned* Wl = Ah + 7680;
#pragma unroll
        for (int ks = 0; ks < 2; ++ks) {
            int kc = ks * 8 + (lane & 3);
            unsigned ah[2][4], al[2][4];
#pragma unroll
            for (int mt = 0; mt < 2; ++mt) {
                int r = wm * 32 + mt * 16 + gr;
                const unsigned* ph = &Ah[r * ST + kc];
                const unsigned* pl = &Al[r * ST + kc];
                ah[mt][0] = ph[0]; ah[mt][1] = ph[8 * ST];
                ah[mt][2] = ph[4]; ah[mt][3] = ph[8 * ST + 4];
                al[mt][0] = pl[0]; al[mt][1] = pl[8 * ST];
                al[mt][2] = pl[4]; al[mt][3] = pl[8 * ST + 4];
            }
#pragma unroll
            for (int nh = 0; nh < 2; ++nh) {
                unsigned bh[4][2], bl[4][2];
#pragma unroll
                for (int j = 0; j < 4; ++j) {
                    int c = wn * 64 + (nh * 4 + j) * 8 + gr;
                    bh[j][0] = Wh[c * ST + kc];
                    bh[j][1] = Wh[c * ST + kc + 4];
                    bl[j][0] = Wl[c * ST + kc];
                    bl[j][1] = Wl[c * ST + kc + 4];
                }
#pragma unroll
                for (int mt = 0; mt < 2; ++mt)
#pragma unroll
                    for (int j = 0; j < 4; ++j) {
                        float* cc = acc[mt][nh * 4 + j];
                        mma_bf16(cc, al[mt], bh[j]);
                        mma_bf16(cc, ah[mt], bl[j]);
                        mma_bf16(cc, ah[mt], bh[j]);
                    }
            }
        }
    };

    if (INSPLIT) {
        issue(0, 0);
#pragma unroll
        for (int ci = 0; ci < NC; ++ci) {
            if (ci + 1 < NC) {
                issue(ci + 1, (ci + 1) & 1);
                cp_wait<1>();
            } else {
                cp_wait<0>();
            }
            __syncthreads();
            compute(ci & 1);
            __syncthreads();
        }
    } else {
        unsigned* Ah = smem;
        unsigned* Al = smem + 2560;
        unsigned* Wh = smem + 5120;
        unsigned* Wl = smem + 7680;
        for (int kb = 0; kb < K; kb += CH) {
            int kp0 = kb >> 1;
            __syncthreads();
            for (int i = tid; i < 512; i += 256) {
                int c = i >> 2, q = (i & 3) * 4;
                *(uint4*)&Wh[c * ST + q] = *(const uint4*)&Wgh[(size_t)c * KP + kp0 + q];
                *(uint4*)&Wl[c * ST + q] = *(const uint4*)&Wgl[(size_t)c * KP + kp0 + q];
            }
            for (int i = tid; i < 128 * 8; i += 256) {
                int r = i >> 3, q = i & 7;
                float4 v = make_float4(0.f, 0.f, 0.f, 0.f);
                if (row0 + r < M)
                    v = *(const float4*)(A + (size_t)(row0 + r) * K + kb + 4 * q);
                if (PRO == 2) {
                    int kg = kb + 4 * q;
                    v.x = fmaxf(0.f, fmaf(v.x, sbnp[kg + 0], sbnp[WN + kg + 0]));
                    v.y = fmaxf(0.f, fmaf(v.y, sbnp[kg + 1], sbnp[WN + kg + 1]));
                    v.z = fmaxf(0.f, fmaf(v.z, sbnp[kg + 2], sbnp[WN + kg + 2]));
                    v.w = fmaxf(0.f, fmaf(v.w, sbnp[kg + 3], sbnp[WN + kg + 3]));
                }
                unsigned h0, l0, h1, l1;
                split_pair(v.x, v.y, h0, l0);
                split_pair(v.z, v.w, h1, l1);
                *(uint2*)&Ah[r * ST + 2 * q] = make_uint2(h0, h1);
                *(uint2*)&Al[r * ST + 2 * q] = make_uint2(l0, l1);
            }
            __syncthreads();
            compute(0);
        }
    }

    // ---------------- epilogue ----------------
    if (POOL) {
        int rbase = row0 + wm * 32 + gr;
        int bt[4];
#pragma unroll
        for (int t = 0; t < 4; ++t) {
            int r = rbase + t * 8;
            bt[t] = (r < M) ? batch[r] : -1;
        }
        bool same = (bt[0] == bt[1]) && (bt[1] == bt[2]) && (bt[2] == bt[3]) && (bt[0] >= 0);
#pragma unroll
        for (int nt = 0; nt < 8; ++nt) {
#pragma unroll
            for (int c = 0; c < 2; ++c) {
                int col = wn * 64 + nt * 8 + (lane & 3) * 2 + c;
                float bb = bias[col];
                float v[4];
                v[0] = fmaxf(0.f, acc[0][nt][c] + bb);
                v[1] = fmaxf(0.f, acc[0][nt][2 + c] + bb);
                v[2] = fmaxf(0.f, acc[1][nt][c] + bb);
                v[3] = fmaxf(0.f, acc[1][nt][2 + c] + bb);
                if (same) {
                    float m = fmaxf(fmaxf(v[0], v[1]), fmaxf(v[2], v[3]));
                    atomicMax((int*)&g_pooled[(size_t)bt[0] * WN + col], __float_as_int(m));
                } else {
#pragma unroll
                    for (int t = 0; t < 4; ++t)
                        if (bt[t] >= 0)
                            atomicMax((int*)&g_pooled[(size_t)bt[t] * WN + col],
                                      __float_as_int(v[t]));
                }
            }
        }

        // ---- fused final MLP: last CTA to finish pooling runs it ----
        __shared__ int lastf;
        __threadfence();
        if (tid == 0) lastf = (atomicAdd(&g_pool_done, 1) == (int)gridDim.x - 1);
        __syncthreads();
        if (!lastf) return;
        if (tid == 0) g_pool_done = 0;   // reset for graph replay

        __shared__ float ys[GMAX][65];
        __shared__ float fsc[64], fsh[64];
        float* W5s = (float*)smem;       // reuse dynamic smem (needs 32 KB of 40 KB)
        for (int i = tid; i < WN * 64; i += 256) W5s[i] = W5[i];
        __syncthreads();

        int g = tid & 63;
        int jb = tid >> 6;
        float a2[16];
#pragma unroll
        for (int j = 0; j < 16; ++j) a2[j] = 0.f;
        if (g < Gn) {
            for (int k = 0; k < WN; ++k) {
                float p = g_pooled[(size_t)g * WN + k];
#pragma unroll
                for (int j = 0; j < 16; ++j)
                    a2[j] = fmaf(p, W5s[k * 64 + jb * 16 + j], a2[j]);
            }
#pragma unroll
            for (int j = 0; j < 16; ++j)
                ys[g][jb * 16 + j] = a2[j] + b5[jb * 16 + j];
        }
        __syncthreads();

        if (tid < 64) {
            float s = 0.f, q = 0.f;
            for (int r = 0; r < Gn; ++r) {
                float v = ys[r][tid];
                s += v;
                q += v * v;
            }
            float inv = 1.0f / (float)Gn;
            float mu = s * inv;
            float var = q * inv - mu * mu;
            float scale = g2[tid] * rsqrtf(var + 1e-5f);
            fsc[tid] = scale;
            fsh[tid] = be2[tid] - mu * scale;
        }
        __syncthreads();

        if (tid < Gn) {
            float o = b6[0];
            for (int j = 0; j < 64; ++j) {
                float v = fmaxf(0.f, fmaf(ys[tid][j], fsc[j], fsh[j]));
                o = fmaf(v, W6[j], o);
            }
            fout[tid] = o;
        }
        return;
    }

    float ss[16], sq[16];
    if (STATS) {
#pragma unroll
        for (int i = 0; i < 16; ++i) { ss[i] = 0.f; sq[i] = 0.f; }
    }

#pragma unroll
    for (int mt = 0; mt < 2; ++mt) {
#pragma unroll
        for (int h = 0; h < 2; ++h) {
            int row = row0 + wm * 32 + mt * 16 + gr + h * 8;
            bool ok = row < M;
#pragma unroll
            for (int nt = 0; nt < 8; ++nt) {
                int col = wn * 64 + nt * 8 + (lane & 3) * 2;
                float b0 = bias ? bias[col] : 0.f;
                float b1 = bias ? bias[col + 1] : 0.f;
                float o0 = acc[mt][nt][h * 2 + 0] + b0;
                float o1 = acc[mt][nt][h * 2 + 1] + b1;
                if (ok)
                    *(float2*)(C + (size_t)row * WN + col) = make_float2(o0, o1);
                if (STATS) {
                    if (!ok) { o0 = 0.f; o1 = 0.f; }
                    ss[nt * 2 + 0] += o0; sq[nt * 2 + 0] += o0 * o0;
                    ss[nt * 2 + 1] += o1; sq[nt * 2 + 1] += o1 * o1;
                }
            }
        }
    }

    if (STATS) {
#pragma unroll
        for (int i = 0; i < 16; ++i) {
#pragma unroll
            for (int o = 4; o <= 16; o <<= 1) {
                ss[i] += __shfl_xor_sync(0xffffffffu, ss[i], o);
                sq[i] += __shfl_xor_sync(0xffffffffu, sq[i], o);
            }
        }
        if (lane < 4) {
#pragma unroll
            for (int nt = 0; nt < 8; ++nt)
#pragma unroll
                for (int c = 0; c < 2; ++c) {
                    int col = wn * 64 + nt * 8 + lane * 2 + c;
                    atomicAdd(&sstat[col], ss[nt * 2 + c]);
                    atomicAdd(&sstat[WN + col], sq[nt * 2 + c]);
                }
        }
        __syncthreads();
        atomicAdd(&g_stats[tid], sstat[tid]);
    }
}

// ---------------- launch ----------------
extern "C" void kernel_launch(void* const* d_in, const int* in_sizes, int n_in,
                              void* d_out, int out_size) {
    const float* x   = (const float*)d_in[0];
    const int*   ei  = (const int*)d_in[1];
    const int*   bat = (const int*)d_in[2];
    const float* W1  = (const float*)d_in[3];
    const float* b1  = (const float*)d_in[4];
    const float* W2  = (const float*)d_in[5];
    const float* b2  = (const float*)d_in[6];
    const float* W3  = (const float*)d_in[7];
    const float* b3  = (const float*)d_in[8];
    const float* g1  = (const float*)d_in[9];
    const float* be1 = (const float*)d_in[10];
    const float* W4  = (const float*)d_in[11];
    const float* b4  = (const float*)d_in[12];
    const float* W5  = (const float*)d_in[13];
    const float* b5  = (const float*)d_in[14];
    const float* g2  = (const float*)d_in[15];
    const float* be2 = (const float*)d_in[16];
    const float* W6  = (const float*)d_in[17];
    const float* b6  = (const float*)d_in[18];

    int N = in_sizes[2];
    int E = in_sizes[1] / 2;
    int G = out_size;
    const int* src = ei;
    const int* dst = ei + E;

    float *B0, *B1, *B2;
    unsigned *S1h, *S1l, *Wsh, *Wsl;
    void *pcnt, *pstats, *ppooled;
    cudaGetSymbolAddress((void**)&B0, g_B0);
    cudaGetSymbolAddress((void**)&B1, g_B1);
    cudaGetSymbolAddress((void**)&B2, g_B2);
    cudaGetSymbolAddress((void**)&S1h, g_S1h);
    cudaGetSymbolAddress((void**)&S1l, g_S1l);
    cudaGetSymbolAddress((void**)&Wsh, g_Wsh);
    cudaGetSymbolAddress((void**)&Wsl, g_Wsl);
    cudaGetSymbolAddress(&pcnt, g_cnt);
    cudaGetSymbolAddress(&pstats, g_stats);
    cudaGetSymbolAddress(&ppooled, g_pooled);

    static cudaStream_t s2 = nullptr;
    static cudaEvent_t evA = nullptr, evB = nullptr;
    if (!s2) {
        cudaStreamCreateWithFlags(&s2, cudaStreamNonBlocking);
        cudaEventCreateWithFlags(&evA, cudaEventDisableTiming);
        cudaEventCreateWithFlags(&evB, cudaEventDisableTiming);
    }

    int nb = (N + 1023) / 1024;
    int gb = (N + 127) / 128;
    int gather_blocks = (int)(((long long)N * 32 + 255) / 256);
    int smem1 = 10240 * 4;     // GEMM4 single stage: 40960
    int smem2 = 20480 * 4;     // GEMM3 double-buffered: 81920
    int smem12 = 27648 * 4;    // fused GEMM1+2: 110592

    cudaFuncSetAttribute(gemm12_kernel,
                         cudaFuncAttributeMaxDynamicSharedMemorySize, smem12);
    cudaFuncSetAttribute(mma_gemm<128, 0, true, true, false>,
                         cudaFuncAttributeMaxDynamicSharedMemorySize, smem2);
    cudaFuncSetAttribute(mma_gemm<128, 2, false, false, true>,
                         cudaFuncAttributeMaxDynamicSharedMemorySize, smem1);

    // ---- fork: CSR build + gather_x on side stream ----
    cudaEventRecord(evA, 0);
    cudaStreamWaitEvent(s2, evA, 0);

    cudaMemsetAsync(pcnt, 0, (size_t)N * sizeof(int), s2);
    deg_kernel<<<(E + 255) / 256, 256, 0, s2>>>(dst, E);
    dinv_kernel<<<(N + 255) / 256, 256, 0, s2>>>(N);
    scan1_kernel<<<nb, 1024, 0, s2>>>(N);
    scan3_kernel<<<(N + 255) / 256, 256, 0, s2>>>(N);
    bin_kernel<<<(E + 255) / 256, 256, 0, s2>>>(src, dst, E);
    gatherx_kernel<<<gather_blocks, 256, 0, s2>>>(x, B2, N);   // Xs -> B2
    cudaEventRecord(evB, s2);

    // main stream: memsets + W pre-splits
    cudaMemsetAsync(pstats, 0, 2 * WN * sizeof(float));
    cudaMemsetAsync(ppooled, 0, (size_t)G * WN * sizeof(float));
    wsplit_kernel<<<8, 256>>>(W1, Wsh + 0, Wsl + 0, 32);
    wsplit_kernel<<<32, 256>>>(W2, Wsh + 8192, Wsl + 8192, 128);
    wsplit_kernel<<<32, 256>>>(W3, Wsh + 16384, Wsl + 16384, 128);
    wsplit_kernel<<<32, 256>>>(W4, Wsh + 24576, Wsl + 24576, 128);

    // join
    cudaStreamWaitEvent(0, evB, 0);

    // fused GEMM1+2: B0 = relu(Xs@W1 + b1) @ W2
    gemm12_kernel<<<gb, 256, smem12>>>(B2, Wsh, Wsl, Wsh + 8192, Wsl + 8192, b1, B0, N);

    // gather+relu -> split S1 (adds self + b2)
    gather_split_kernel<<<gather_blocks, 256>>>(B0, b2, S1h, S1l, N);

    // GEMM3 (pipelined): y = S1@W3 + b3 -> B1 (f32) + stats
    mma_gemm<128, 0, true, true, false><<<gb, 256, smem2>>>(
        nullptr, S1h, S1l, Wsh + 16384, Wsl + 16384, b3, B1, nullptr, nullptr, nullptr,
        nullptr, nullptr, nullptr, nullptr, nullptr, nullptr, nullptr, G, N);

    // GEMM4: relu(bn(B1))@W4 + b4, fused max-pool + last-CTA final MLP -> d_out
    mma_gemm<128, 2, false, false, true><<<gb, 256, smem1>>>(
        B1, nullptr, nullptr, Wsh + 24576, Wsl + 24576, b4, nullptr, g1, be1, bat,
        W5, b5, g2, be2, W6, b6, (float*)d_out, G, N);
}